// round 4
// baseline (speedup 1.0000x reference)
#include <cuda_runtime.h>

// ---------------------------------------------------------------------------
// MoE FFN (E=8, top-2, capacity 1280/slot), T=8192, D=1024, H=2048, fp32.
// Pipeline: memset(out) -> router -> capacity scan/list build ->
//           gathered gate/up GEMM + SwiGLU -> gathered down GEMM + scatter.
// ---------------------------------------------------------------------------

namespace {
constexpr int kT    = 8192;   // B*S
constexpr int kD    = 1024;
constexpr int kH    = 2048;
constexpr int kE    = 8;
constexpr int kK    = 2;
constexpr int kCap  = 1280;   // int(1.25 * T / E)
constexpr int kMaxN = 2 * kCap;  // 2560, max tokens per expert (both slots)
}

// Scratch (device globals: allocation-free rule).
__device__ int   g_topi[kT * kK];
__device__ float g_topw[kT * kK];
__device__ int   g_tok[kE * kMaxN];
__device__ float g_wt [kE * kMaxN];
__device__ int   g_cnt[kE];
__device__ float g_act[(size_t)kE * kMaxN * kH];   // silu(g)*u scratch, fp32

// ---- packed f32x2 helpers (Blackwell FFMA2 path) ---------------------------
__device__ __forceinline__ unsigned long long pk2(float v) {
    unsigned long long r;
    unsigned u = __float_as_uint(v);
    asm("mov.b64 %0, {%1, %1};" : "=l"(r) : "r"(u));
    return r;
}
__device__ __forceinline__ void ffma2(unsigned long long& d,
                                      unsigned long long a,
                                      unsigned long long b) {
    asm("fma.rn.f32x2 %0, %1, %2, %0;" : "+l"(d) : "l"(a), "l"(b));
}
__device__ __forceinline__ float lo32(unsigned long long v) {
    return __uint_as_float((unsigned)(v & 0xffffffffull));
}
__device__ __forceinline__ float hi32(unsigned long long v) {
    return __uint_as_float((unsigned)(v >> 32));
}

// ---------------------------------------------------------------------------
// Router: one warp per token. logits = x_t . gate_w[e], softmax, top-2,
// normalized weights. Writes g_topi / g_topw.
// ---------------------------------------------------------------------------
__global__ __launch_bounds__(256) void router_kernel(
    const float* __restrict__ x, const float* __restrict__ gw) {
    int lane = threadIdx.x & 31;
    int warp = threadIdx.x >> 5;
    int t = blockIdx.x * 8 + warp;

    const float* xr = x + (size_t)t * kD;
    float xv[32];
#pragma unroll
    for (int i = 0; i < 32; i++) xv[i] = xr[lane + 32 * i];

    float lg[kE];
#pragma unroll
    for (int e = 0; e < kE; e++) {
        const float* g = gw + e * kD;
        float s = 0.f;
#pragma unroll
        for (int i = 0; i < 32; i++) s = fmaf(xv[i], g[lane + 32 * i], s);
#pragma unroll
        for (int o = 16; o > 0; o >>= 1) s += __shfl_xor_sync(0xffffffffu, s, o);
        lg[e] = s;
    }

    if (lane == 0) {
        float mx = lg[0];
#pragma unroll
        for (int e = 1; e < kE; e++) mx = fmaxf(mx, lg[e]);
        float p[kE];
        float den = 0.f;
#pragma unroll
        for (int e = 0; e < kE; e++) { p[e] = expf(lg[e] - mx); den += p[e]; }
        int i1 = 0; float p1 = p[0];
#pragma unroll
        for (int e = 1; e < kE; e++) if (p[e] > p1) { p1 = p[e]; i1 = e; }
        int i2 = (i1 == 0) ? 1 : 0; float p2 = p[i2];
#pragma unroll
        for (int e = 0; e < kE; e++)
            if (e != i1 && p[e] > p2) { p2 = p[e]; i2 = e; }
        float pn1 = p1 / den, pn2 = p2 / den;
        float inv = 1.f / (pn1 + pn2 + 1e-9f);
        g_topi[t * 2 + 0] = i1;
        g_topi[t * 2 + 1] = i2;
        g_topw[t * 2 + 0] = pn1 * inv;
        g_topw[t * 2 + 1] = pn2 * inv;
    }
}

// ---------------------------------------------------------------------------
// Capacity ranking + compacted per-expert lists. One CTA, 16 warps; warp w
// handles slot k=w/8, expert e=w%8. rank = #prior tokens with same (k,e)
// (exactly the reference cumsum-1). A kept token's rank is its position in
// the compacted (k,e) segment, so writes are conflict-free, no atomics.
// ---------------------------------------------------------------------------
__global__ __launch_bounds__(512) void build_lists_kernel() {
    __shared__ int kept[kK][kE];
    int w = threadIdx.x >> 5, lane = threadIdx.x & 31;
    int k = w >> 3, e = w & 7;

    // pass 1: total assignment count for (k, e)
    int cnt = 0;
#pragma unroll 4
    for (int t0 = 0; t0 < kT; t0 += 32) {
        int t = t0 + lane;
        int sel = (g_topi[t * 2 + k] == e);
        unsigned m = __ballot_sync(0xffffffffu, sel);
        cnt += __popc(m);
    }
    if (lane == 0) kept[k][e] = min(cnt, kCap);
    __syncthreads();

    int off = (k == 0) ? 0 : kept[0][e];
    if (w < kE && lane == 0) g_cnt[w] = kept[0][w] + kept[1][w];

    // pass 2: scatter kept tokens at their rank position
    int rank = 0;
#pragma unroll 4
    for (int t0 = 0; t0 < kT; t0 += 32) {
        int t = t0 + lane;
        int sel = (g_topi[t * 2 + k] == e);
        unsigned m = __ballot_sync(0xffffffffu, sel);
        int r = rank + __popc(m & ((1u << lane) - 1u));
        if (sel && r < kCap) {
            int idx = e * kMaxN + off + r;
            g_tok[idx] = t;
            g_wt[idx]  = g_topw[t * 2 + k];
        }
        rank += __popc(m);
    }
}

// ---------------------------------------------------------------------------
// Gate/Up GEMM + SwiGLU: act[e][m][n] = silu(X_g @ Wg_e^T) * (X_g @ Wu_e^T)
// Tile: BM=128 tokens x BN=64 hidden, BK=16. Thread: 8x4 outputs for BOTH
// gate and up (two f32x2 accumulator pairs per 8x4).
// ---------------------------------------------------------------------------
#define BM3 128
#define BN3 64
#define BK3 16

__global__ __launch_bounds__(256, 2) void gateup_kernel(
    const float* __restrict__ x,
    const float* __restrict__ wg,
    const float* __restrict__ wu) {
    int e  = blockIdx.z;
    int ne = g_cnt[e];
    int m0 = blockIdx.y * BM3;
    if (m0 >= ne) return;
    int n0 = blockIdx.x * BN3;

    __shared__ __align__(16) float As[BK3][BM3 + 4];
    __shared__ __align__(16) float Gs[BK3][BN3 + 4];
    __shared__ __align__(16) float Us[BK3][BN3 + 4];
    __shared__ int toks[BM3];

    int tx = threadIdx.x;
    if (tx < BM3) {
        int m = m0 + tx;
        toks[tx] = (m < ne) ? g_tok[e * kMaxN + m] : -1;
    }
    __syncthreads();

    int tm = tx >> 4, tn = tx & 15;  // 16x16 thread grid

    unsigned long long accg[8][2], accu[8][2];
#pragma unroll
    for (int i = 0; i < 8; i++)
#pragma unroll
        for (int j = 0; j < 2; j++) { accg[i][j] = 0ull; accu[i][j] = 0ull; }

    const float* wge = wg + (size_t)e * kH * kD;
    const float* wue = wu + (size_t)e * kH * kD;

    for (int k0 = 0; k0 < kD; k0 += BK3) {
#pragma unroll
        for (int i = 0; i < 8; i++) {          // A: 128x16 = 2048, 8/thread
            int id = tx + 256 * i;
            int m = id >> 4, k = id & 15;
            int tok = toks[m];
            As[k][m] = (tok >= 0) ? x[(size_t)tok * kD + k0 + k] : 0.f;
        }
#pragma unroll
        for (int i = 0; i < 4; i++) {          // B: 64x16 = 1024 each
            int id = tx + 256 * i;
            int n = id >> 4, k = id & 15;
            size_t off = (size_t)(n0 + n) * kD + k0 + k;
            Gs[k][n] = wge[off];
            Us[k][n] = wue[off];
        }
        __syncthreads();

#pragma unroll
        for (int k = 0; k < BK3; k++) {
            float4 a0 = *(const float4*)&As[k][tm * 8];
            float4 a1 = *(const float4*)&As[k][tm * 8 + 4];
            ulonglong2 bg = *(const ulonglong2*)&Gs[k][tn * 4];
            ulonglong2 bu = *(const ulonglong2*)&Us[k][tn * 4];
            unsigned long long pa[8];
            pa[0] = pk2(a0.x); pa[1] = pk2(a0.y); pa[2] = pk2(a0.z); pa[3] = pk2(a0.w);
            pa[4] = pk2(a1.x); pa[5] = pk2(a1.y); pa[6] = pk2(a1.z); pa[7] = pk2(a1.w);
#pragma unroll
            for (int i = 0; i < 8; i++) {
                ffma2(accg[i][0], pa[i], bg.x);
                ffma2(accg[i][1], pa[i], bg.y);
                ffma2(accu[i][0], pa[i], bu.x);
                ffma2(accu[i][1], pa[i], bu.y);
            }
        }
        __syncthreads();
    }

    // epilogue: act = silu(g) * u
#pragma unroll
    for (int i = 0; i < 8; i++) {
        int m = m0 + tm * 8 + i;
        if (m < ne) {
            float* dst = g_act + ((size_t)e * kMaxN + m) * kH + n0 + tn * 4;
#pragma unroll
            for (int j = 0; j < 2; j++) {
                float g0 = lo32(accg[i][j]), g1 = hi32(accg[i][j]);
                float u0 = lo32(accu[i][j]), u1 = hi32(accu[i][j]);
                float s0 = g0 / (1.f + expf(-g0));
                float s1 = g1 / (1.f + expf(-g1));
                dst[2 * j + 0] = s0 * u0;
                dst[2 * j + 1] = s1 * u1;
            }
        }
    }
}

// ---------------------------------------------------------------------------
// Down-proj GEMM + weighted scatter: out[tok[m]] += w[m] * (act @ Wd_e^T)
// Tile: BM=128 x BN=128, BK=16, 8x8 per thread via f32x2.
// ---------------------------------------------------------------------------
#define BM4 128
#define BN4 128
#define BK4 16

__global__ __launch_bounds__(256, 2) void down_kernel(
    const float* __restrict__ wd, float* __restrict__ out) {
    int e  = blockIdx.z;
    int ne = g_cnt[e];
    int m0 = blockIdx.y * BM4;
    if (m0 >= ne) return;
    int n0 = blockIdx.x * BN4;

    __shared__ __align__(16) float As[BK4][BM4 + 4];
    __shared__ __align__(16) float Bs[BK4][BN4 + 4];
    __shared__ int   toks[BM4];
    __shared__ float wts[BM4];

    int tx = threadIdx.x;
    if (tx < BM4) {
        int m = m0 + tx;
        toks[tx] = (m < ne) ? g_tok[e * kMaxN + m] : -1;
        wts[tx]  = (m < ne) ? g_wt[e * kMaxN + m] : 0.f;
    }
    __syncthreads();

    int tm = tx >> 4, tn = tx & 15;

    unsigned long long acc[8][4];
#pragma unroll
    for (int i = 0; i < 8; i++)
#pragma unroll
        for (int j = 0; j < 4; j++) acc[i][j] = 0ull;

    const float* wde  = wd + (size_t)e * kD * kH;
    const float* acte = g_act + (size_t)e * kMaxN * kH;

    for (int k0 = 0; k0 < kH; k0 += BK4) {
#pragma unroll
        for (int i = 0; i < 8; i++) {          // A and B: 128x16 each, 8/thread
            int id = tx + 256 * i;
            int m = id >> 4, k = id & 15;
            As[k][m] = (m0 + m < ne) ? acte[(size_t)(m0 + m) * kH + k0 + k] : 0.f;
            Bs[k][m] = wde[(size_t)(n0 + m) * kH + k0 + k];
        }
        __syncthreads();

#pragma unroll
        for (int k = 0; k < BK4; k++) {
            float4 a0 = *(const float4*)&As[k][tm * 8];
            float4 a1 = *(const float4*)&As[k][tm * 8 + 4];
            ulonglong2 b0 = *(const ulonglong2*)&Bs[k][tn * 8];
            ulonglong2 b1 = *(const ulonglong2*)&Bs[k][tn * 8 + 4];
            unsigned long long pa[8];
            pa[0] = pk2(a0.x); pa[1] = pk2(a0.y); pa[2] = pk2(a0.z); pa[3] = pk2(a0.w);
            pa[4] = pk2(a1.x); pa[5] = pk2(a1.y); pa[6] = pk2(a1.z); pa[7] = pk2(a1.w);
#pragma unroll
            for (int i = 0; i < 8; i++) {
                ffma2(acc[i][0], pa[i], b0.x);
                ffma2(acc[i][1], pa[i], b0.y);
                ffma2(acc[i][2], pa[i], b1.x);
                ffma2(acc[i][3], pa[i], b1.y);
            }
        }
        __syncthreads();
    }

    // epilogue: weighted scatter-add (REDG; token appears in <=2 experts)
#pragma unroll
    for (int i = 0; i < 8; i++) {
        int m = m0 + tm * 8 + i;
        if (m < ne) {
            int   tok = toks[tm * 8 + i];
            float w   = wts[tm * 8 + i];
            float* orow = out + (size_t)tok * kD + n0 + tn * 8;
#pragma unroll
            for (int j = 0; j < 4; j++) {
                atomicAdd(&orow[2 * j + 0], w * lo32(acc[i][j]));
                atomicAdd(&orow[2 * j + 1], w * hi32(acc[i][j]));
            }
        }
    }
}

// ---------------------------------------------------------------------------
// Launch. Inputs: 0=x (T,D), 1=gate_w (E,D), 2=gate_proj_w (E,H,D),
// 3=up_proj_w (E,H,D), 4=down_proj_w (E,D,H). Output: (T,D) fp32.
// ---------------------------------------------------------------------------
extern "C" void kernel_launch(void* const* d_in, const int* in_sizes, int n_in,
                              void* d_out, int out_size) {
    (void)in_sizes; (void)n_in;
    const float* x  = (const float*)d_in[0];
    const float* gw = (const float*)d_in[1];
    const float* wg = (const float*)d_in[2];
    const float* wu = (const float*)d_in[3];
    const float* wd = (const float*)d_in[4];
    float* out = (float*)d_out;

    cudaMemsetAsync(out, 0, (size_t)out_size * sizeof(float));

    router_kernel<<<kT / 8, 256>>>(x, gw);
    build_lists_kernel<<<1, 512>>>();

    dim3 g3(kH / BN3, kMaxN / BM3, kE);   // (32, 20, 8)
    gateup_kernel<<<g3, 256>>>(x, wg, wu);

    dim3 g4(kD / BN4, kMaxN / BM4, kE);   // (8, 20, 8)
    down_kernel<<<g4, 256>>>(wd, out);
}

// round 5
// speedup vs baseline: 1.0058x; 1.0058x over previous
#include <cuda_runtime.h>

// ---------------------------------------------------------------------------
// MoE FFN (E=8, top-2, capacity 1280/slot), T=8192, D=1024, H=2048, fp32.
// Pipeline: memset(out) -> router -> capacity scan/list build ->
//           gathered gate/up GEMM + SwiGLU -> gathered down GEMM + scatter.
// ---------------------------------------------------------------------------

namespace {
constexpr int kT    = 8192;   // B*S
constexpr int kD    = 1024;
constexpr int kH    = 2048;
constexpr int kE    = 8;
constexpr int kK    = 2;
constexpr int kCap  = 1280;   // int(1.25 * T / E)
constexpr int kMaxN = 2 * kCap;  // 2560, max tokens per expert (both slots)
}

// Scratch (device globals: allocation-free rule).
__device__ int   g_topi[kT * kK];
__device__ float g_topw[kT * kK];
__device__ int   g_tok[kE * kMaxN];
__device__ float g_wt [kE * kMaxN];
__device__ int   g_cnt[kE];
__device__ float g_act[(size_t)kE * kMaxN * kH];   // silu(g)*u scratch, fp32

// ---- packed f32x2 helpers (Blackwell FFMA2 path) ---------------------------
__device__ __forceinline__ unsigned long long pk2(float v) {
    unsigned long long r;
    unsigned u = __float_as_uint(v);
    asm("mov.b64 %0, {%1, %1};" : "=l"(r) : "r"(u));
    return r;
}
__device__ __forceinline__ void ffma2(unsigned long long& d,
                                      unsigned long long a,
                                      unsigned long long b) {
    asm("fma.rn.f32x2 %0, %1, %2, %0;" : "+l"(d) : "l"(a), "l"(b));
}
__device__ __forceinline__ float lo32(unsigned long long v) {
    return __uint_as_float((unsigned)(v & 0xffffffffull));
}
__device__ __forceinline__ float hi32(unsigned long long v) {
    return __uint_as_float((unsigned)(v >> 32));
}

// ---------------------------------------------------------------------------
// Router: one warp per token. logits = x_t . gate_w[e], softmax, top-2,
// normalized weights. Writes g_topi / g_topw.
// ---------------------------------------------------------------------------
__global__ __launch_bounds__(256) void router_kernel(
    const float* __restrict__ x, const float* __restrict__ gw) {
    int lane = threadIdx.x & 31;
    int warp = threadIdx.x >> 5;
    int t = blockIdx.x * 8 + warp;

    const float* xr = x + (size_t)t * kD;
    float xv[32];
#pragma unroll
    for (int i = 0; i < 32; i++) xv[i] = xr[lane + 32 * i];

    float lg[kE];
#pragma unroll
    for (int e = 0; e < kE; e++) {
        const float* g = gw + e * kD;
        float s = 0.f;
#pragma unroll
        for (int i = 0; i < 32; i++) s = fmaf(xv[i], g[lane + 32 * i], s);
#pragma unroll
        for (int o = 16; o > 0; o >>= 1) s += __shfl_xor_sync(0xffffffffu, s, o);
        lg[e] = s;
    }

    if (lane == 0) {
        float mx = lg[0];
#pragma unroll
        for (int e = 1; e < kE; e++) mx = fmaxf(mx, lg[e]);
        float p[kE];
        float den = 0.f;
#pragma unroll
        for (int e = 0; e < kE; e++) { p[e] = expf(lg[e] - mx); den += p[e]; }
        int i1 = 0; float p1 = p[0];
#pragma unroll
        for (int e = 1; e < kE; e++) if (p[e] > p1) { p1 = p[e]; i1 = e; }
        int i2 = (i1 == 0) ? 1 : 0; float p2 = p[i2];
#pragma unroll
        for (int e = 0; e < kE; e++)
            if (e != i1 && p[e] > p2) { p2 = p[e]; i2 = e; }
        float pn1 = p1 / den, pn2 = p2 / den;
        float inv = 1.f / (pn1 + pn2 + 1e-9f);
        g_topi[t * 2 + 0] = i1;
        g_topi[t * 2 + 1] = i2;
        g_topw[t * 2 + 0] = pn1 * inv;
        g_topw[t * 2 + 1] = pn2 * inv;
    }
}

// ---------------------------------------------------------------------------
// Capacity ranking + compacted per-expert lists. One CTA, 16 warps; warp w
// handles slot k=w/8, expert e=w%8. rank = #prior tokens with same (k,e)
// (exactly the reference cumsum-1). A kept token's rank is its position in
// the compacted (k,e) segment, so writes are conflict-free, no atomics.
// ---------------------------------------------------------------------------
__global__ __launch_bounds__(512) void build_lists_kernel() {
    __shared__ int kept[kK][kE];
    int w = threadIdx.x >> 5, lane = threadIdx.x & 31;
    int k = w >> 3, e = w & 7;

    // pass 1: total assignment count for (k, e)
    int cnt = 0;
#pragma unroll 4
    for (int t0 = 0; t0 < kT; t0 += 32) {
        int t = t0 + lane;
        int sel = (g_topi[t * 2 + k] == e);
        unsigned m = __ballot_sync(0xffffffffu, sel);
        cnt += __popc(m);
    }
    if (lane == 0) kept[k][e] = min(cnt, kCap);
    __syncthreads();

    int off = (k == 0) ? 0 : kept[0][e];
    if (w < kE && lane == 0) g_cnt[w] = kept[0][w] + kept[1][w];

    // pass 2: scatter kept tokens at their rank position
    int rank = 0;
#pragma unroll 4
    for (int t0 = 0; t0 < kT; t0 += 32) {
        int t = t0 + lane;
        int sel = (g_topi[t * 2 + k] == e);
        unsigned m = __ballot_sync(0xffffffffu, sel);
        int r = rank + __popc(m & ((1u << lane) - 1u));
        if (sel && r < kCap) {
            int idx = e * kMaxN + off + r;
            g_tok[idx] = t;
            g_wt[idx]  = g_topw[t * 2 + k];
        }
        rank += __popc(m);
    }
}

// ---------------------------------------------------------------------------
// Gate/Up GEMM + SwiGLU: act[e][m][n] = silu(X_g @ Wg_e^T) * (X_g @ Wu_e^T)
// Tile: BM=128 tokens x BN=64 hidden, BK=16. Thread: 8x4 outputs for BOTH
// gate and up (two f32x2 accumulator pairs per 8x4).
// ---------------------------------------------------------------------------
#define BM3 128
#define BN3 64
#define BK3 16

__global__ __launch_bounds__(256, 2) void gateup_kernel(
    const float* __restrict__ x,
    const float* __restrict__ wg,
    const float* __restrict__ wu) {
    int e  = blockIdx.z;
    int ne = g_cnt[e];
    int m0 = blockIdx.y * BM3;
    if (m0 >= ne) return;
    int n0 = blockIdx.x * BN3;

    __shared__ __align__(16) float As[BK3][BM3 + 4];
    __shared__ __align__(16) float Gs[BK3][BN3 + 4];
    __shared__ __align__(16) float Us[BK3][BN3 + 4];
    __shared__ int toks[BM3];

    int tx = threadIdx.x;
    if (tx < BM3) {
        int m = m0 + tx;
        toks[tx] = (m < ne) ? g_tok[e * kMaxN + m] : -1;
    }
    __syncthreads();

    int tm = tx >> 4, tn = tx & 15;  // 16x16 thread grid

    unsigned long long accg[8][2], accu[8][2];
#pragma unroll
    for (int i = 0; i < 8; i++)
#pragma unroll
        for (int j = 0; j < 2; j++) { accg[i][j] = 0ull; accu[i][j] = 0ull; }

    const float* wge = wg + (size_t)e * kH * kD;
    const float* wue = wu + (size_t)e * kH * kD;

    for (int k0 = 0; k0 < kD; k0 += BK3) {
#pragma unroll
        for (int i = 0; i < 8; i++) {          // A: 128x16 = 2048, 8/thread
            int id = tx + 256 * i;
            int m = id >> 4, k = id & 15;
            int tok = toks[m];
            As[k][m] = (tok >= 0) ? x[(size_t)tok * kD + k0 + k] : 0.f;
        }
#pragma unroll
        for (int i = 0; i < 4; i++) {          // B: 64x16 = 1024 each
            int id = tx + 256 * i;
            int n = id >> 4, k = id & 15;
            size_t off = (size_t)(n0 + n) * kD + k0 + k;
            Gs[k][n] = wge[off];
            Us[k][n] = wue[off];
        }
        __syncthreads();

#pragma unroll
        for (int k = 0; k < BK3; k++) {
            float4 a0 = *(const float4*)&As[k][tm * 8];
            float4 a1 = *(const float4*)&As[k][tm * 8 + 4];
            ulonglong2 bg = *(const ulonglong2*)&Gs[k][tn * 4];
            ulonglong2 bu = *(const ulonglong2*)&Us[k][tn * 4];
            unsigned long long pa[8];
            pa[0] = pk2(a0.x); pa[1] = pk2(a0.y); pa[2] = pk2(a0.z); pa[3] = pk2(a0.w);
            pa[4] = pk2(a1.x); pa[5] = pk2(a1.y); pa[6] = pk2(a1.z); pa[7] = pk2(a1.w);
#pragma unroll
            for (int i = 0; i < 8; i++) {
                ffma2(accg[i][0], pa[i], bg.x);
                ffma2(accg[i][1], pa[i], bg.y);
                ffma2(accu[i][0], pa[i], bu.x);
                ffma2(accu[i][1], pa[i], bu.y);
            }
        }
        __syncthreads();
    }

    // epilogue: act = silu(g) * u
#pragma unroll
    for (int i = 0; i < 8; i++) {
        int m = m0 + tm * 8 + i;
        if (m < ne) {
            float* dst = g_act + ((size_t)e * kMaxN + m) * kH + n0 + tn * 4;
#pragma unroll
            for (int j = 0; j < 2; j++) {
                float g0 = lo32(accg[i][j]), g1 = hi32(accg[i][j]);
                float u0 = lo32(accu[i][j]), u1 = hi32(accu[i][j]);
                float s0 = g0 / (1.f + expf(-g0));
                float s1 = g1 / (1.f + expf(-g1));
                dst[2 * j + 0] = s0 * u0;
                dst[2 * j + 1] = s1 * u1;
            }
        }
    }
}

// ---------------------------------------------------------------------------
// Down-proj GEMM + weighted scatter: out[tok[m]] += w[m] * (act @ Wd_e^T)
// Tile: BM=128 x BN=128, BK=16, 8x8 per thread via f32x2.
// ---------------------------------------------------------------------------
#define BM4 128
#define BN4 128
#define BK4 16

__global__ __launch_bounds__(256, 2) void down_kernel(
    const float* __restrict__ wd, float* __restrict__ out) {
    int e  = blockIdx.z;
    int ne = g_cnt[e];
    int m0 = blockIdx.y * BM4;
    if (m0 >= ne) return;
    int n0 = blockIdx.x * BN4;

    __shared__ __align__(16) float As[BK4][BM4 + 4];
    __shared__ __align__(16) float Bs[BK4][BN4 + 4];
    __shared__ int   toks[BM4];
    __shared__ float wts[BM4];

    int tx = threadIdx.x;
    if (tx < BM4) {
        int m = m0 + tx;
        toks[tx] = (m < ne) ? g_tok[e * kMaxN + m] : -1;
        wts[tx]  = (m < ne) ? g_wt[e * kMaxN + m] : 0.f;
    }
    __syncthreads();

    int tm = tx >> 4, tn = tx & 15;

    unsigned long long acc[8][4];
#pragma unroll
    for (int i = 0; i < 8; i++)
#pragma unroll
        for (int j = 0; j < 4; j++) acc[i][j] = 0ull;

    const float* wde  = wd + (size_t)e * kD * kH;
    const float* acte = g_act + (size_t)e * kMaxN * kH;

    for (int k0 = 0; k0 < kH; k0 += BK4) {
#pragma unroll
        for (int i = 0; i < 8; i++) {          // A and B: 128x16 each, 8/thread
            int id = tx + 256 * i;
            int m = id >> 4, k = id & 15;
            As[k][m] = (m0 + m < ne) ? acte[(size_t)(m0 + m) * kH + k0 + k] : 0.f;
            Bs[k][m] = wde[(size_t)(n0 + m) * kH + k0 + k];
        }
        __syncthreads();

#pragma unroll
        for (int k = 0; k < BK4; k++) {
            float4 a0 = *(const float4*)&As[k][tm * 8];
            float4 a1 = *(const float4*)&As[k][tm * 8 + 4];
            ulonglong2 b0 = *(const ulonglong2*)&Bs[k][tn * 8];
            ulonglong2 b1 = *(const ulonglong2*)&Bs[k][tn * 8 + 4];
            unsigned long long pa[8];
            pa[0] = pk2(a0.x); pa[1] = pk2(a0.y); pa[2] = pk2(a0.z); pa[3] = pk2(a0.w);
            pa[4] = pk2(a1.x); pa[5] = pk2(a1.y); pa[6] = pk2(a1.z); pa[7] = pk2(a1.w);
#pragma unroll
            for (int i = 0; i < 8; i++) {
                ffma2(acc[i][0], pa[i], b0.x);
                ffma2(acc[i][1], pa[i], b0.y);
                ffma2(acc[i][2], pa[i], b1.x);
                ffma2(acc[i][3], pa[i], b1.y);
            }
        }
        __syncthreads();
    }

    // epilogue: weighted scatter-add (REDG; token appears in <=2 experts)
#pragma unroll
    for (int i = 0; i < 8; i++) {
        int m = m0 + tm * 8 + i;
        if (m < ne) {
            int   tok = toks[tm * 8 + i];
            float w   = wts[tm * 8 + i];
            float* orow = out + (size_t)tok * kD + n0 + tn * 8;
#pragma unroll
            for (int j = 0; j < 4; j++) {
                atomicAdd(&orow[2 * j + 0], w * lo32(acc[i][j]));
                atomicAdd(&orow[2 * j + 1], w * hi32(acc[i][j]));
            }
        }
    }
}

// ---------------------------------------------------------------------------
// Launch. Inputs: 0=x (T,D), 1=gate_w (E,D), 2=gate_proj_w (E,H,D),
// 3=up_proj_w (E,H,D), 4=down_proj_w (E,D,H). Output: (T,D) fp32.
// ---------------------------------------------------------------------------
extern "C" void kernel_launch(void* const* d_in, const int* in_sizes, int n_in,
                              void* d_out, int out_size) {
    (void)in_sizes; (void)n_in;
    const float* x  = (const float*)d_in[0];
    const float* gw = (const float*)d_in[1];
    const float* wg = (const float*)d_in[2];
    const float* wu = (const float*)d_in[3];
    const float* wd = (const float*)d_in[4];
    float* out = (float*)d_out;

    cudaMemsetAsync(out, 0, (size_t)out_size * sizeof(float));

    router_kernel<<<kT / 8, 256>>>(x, gw);
    build_lists_kernel<<<1, 512>>>();

    dim3 g3(kH / BN3, kMaxN / BM3, kE);   // (32, 20, 8)
    gateup_kernel<<<g3, 256>>>(x, wg, wu);

    dim3 g4(kD / BN4, kMaxN / BM4, kE);   // (8, 20, 8)
    down_kernel<<<g4, 256>>>(wd, out);
}

// round 10
// speedup vs baseline: 1.5206x; 1.5119x over previous
#include <cuda_runtime.h>
#include <cuda_bf16.h>
#include <cstdint>

namespace {
constexpr int kT = 8192, kD = 1024, kH = 2048, kE = 8, kK = 2;
constexpr int kCap = 1280, kMaxN = 2560;
}

// ---------------- device scratch (zero-init at module load) ----------------
// NOTE: these symbols are ONLY referenced from device code. Passing them as
// kernel arguments from host code silently binds the host shadow copy (ATS
// makes it readable on GB300!) — that was the R7/R8 zero-output bug.
__device__ int   g_topi[kT * kK];
__device__ float g_topw[kT * kK];
__device__ int   g_tok[kE * kMaxN];
__device__ float g_wt [kE * kMaxN];
__device__ int   g_cnt[kE];
// All operand buffers: [row][ hi(K) | lo(K) ] bf16.
__device__ __align__(128) __nv_bfloat16 g_a  [(size_t)kE * kMaxN * 2 * kD];
__device__ __align__(128) __nv_bfloat16 g_wg [(size_t)kE * kH * 2 * kD];
__device__ __align__(128) __nv_bfloat16 g_wu [(size_t)kE * kH * 2 * kD];
__device__ __align__(128) __nv_bfloat16 g_wd [(size_t)kE * kD * 2 * kH];
__device__ __align__(128) __nv_bfloat16 g_act[(size_t)kE * kMaxN * 2 * kH];

// ---------------- PTX helpers (baseline sm_80-era ISA only) ----------------
__device__ __forceinline__ uint32_t smem_u32(const void* p) {
    uint32_t a;
    asm("{ .reg .u64 t; cvta.to.shared.u64 t, %1; cvt.u32.u64 %0, t; }" : "=r"(a) : "l"(p));
    return a;
}
__device__ __forceinline__ void cp16(uint32_t d, const void* s) {
    asm volatile("cp.async.cg.shared.global [%0], [%1], 16;" :: "r"(d), "l"(s));
}
__device__ __forceinline__ void cp_commit() { asm volatile("cp.async.commit_group;" ::: "memory"); }
template <int N> __device__ __forceinline__ void cp_wait() {
    asm volatile("cp.async.wait_group %0;" :: "n"(N) : "memory");
}
__device__ __forceinline__ void ldsm4(uint32_t* r, uint32_t a) {
    asm volatile("ldmatrix.sync.aligned.m8n8.x4.shared.b16 {%0,%1,%2,%3}, [%4];"
                 : "=r"(r[0]), "=r"(r[1]), "=r"(r[2]), "=r"(r[3]) : "r"(a));
}
__device__ __forceinline__ void ldsm2(uint32_t* r, uint32_t a) {
    asm volatile("ldmatrix.sync.aligned.m8n8.x2.shared.b16 {%0,%1}, [%2];"
                 : "=r"(r[0]), "=r"(r[1]) : "r"(a));
}
__device__ __forceinline__ void mma16816(float* d, const uint32_t* a, const uint32_t* b) {
    asm volatile(
        "mma.sync.aligned.m16n8k16.row.col.f32.bf16.bf16.f32 "
        "{%0,%1,%2,%3}, {%4,%5,%6,%7}, {%8,%9}, {%0,%1,%2,%3};"
        : "+f"(d[0]), "+f"(d[1]), "+f"(d[2]), "+f"(d[3])
        : "r"(a[0]), "r"(a[1]), "r"(a[2]), "r"(a[3]), "r"(b[0]), "r"(b[1]));
}
__device__ __forceinline__ uint32_t pack2(__nv_bfloat16 a, __nv_bfloat16 b) {
    __nv_bfloat162 t(a, b);
    return *reinterpret_cast<uint32_t*>(&t);
}

// ---------------- router (verified in R3) ----------------
__global__ __launch_bounds__(256) void router_kernel(const float* __restrict__ x,
                                                     const float* __restrict__ gw) {
    int lane = threadIdx.x & 31, warp = threadIdx.x >> 5;
    int t = blockIdx.x * 8 + warp;
    const float* xr = x + (size_t)t * kD;
    float xv[32];
#pragma unroll
    for (int i = 0; i < 32; i++) xv[i] = xr[lane + 32 * i];
    float lg[kE];
#pragma unroll
    for (int e = 0; e < kE; e++) {
        const float* g = gw + e * kD;
        float s = 0.f;
#pragma unroll
        for (int i = 0; i < 32; i++) s = fmaf(xv[i], g[lane + 32 * i], s);
#pragma unroll
        for (int o = 16; o > 0; o >>= 1) s += __shfl_xor_sync(0xffffffffu, s, o);
        lg[e] = s;
    }
    if (lane == 0) {
        float mx = lg[0];
#pragma unroll
        for (int e = 1; e < kE; e++) mx = fmaxf(mx, lg[e]);
        float p[kE], den = 0.f;
#pragma unroll
        for (int e = 0; e < kE; e++) { p[e] = expf(lg[e] - mx); den += p[e]; }
        int i1 = 0; float p1 = p[0];
#pragma unroll
        for (int e = 1; e < kE; e++) if (p[e] > p1) { p1 = p[e]; i1 = e; }
        int i2 = (i1 == 0) ? 1 : 0; float p2 = p[i2];
#pragma unroll
        for (int e = 0; e < kE; e++) if (e != i1 && p[e] > p2) { p2 = p[e]; i2 = e; }
        float a = p1 / den, b = p2 / den, inv = 1.f / (a + b + 1e-9f);
        g_topi[t * 2] = i1; g_topi[t * 2 + 1] = i2;
        g_topw[t * 2] = a * inv; g_topw[t * 2 + 1] = b * inv;
    }
}

// ---------------- capacity lists (verified in R3) ----------------
__global__ __launch_bounds__(512) void build_lists_kernel() {
    __shared__ int kept[kK][kE];
    int w = threadIdx.x >> 5, lane = threadIdx.x & 31;
    int k = w >> 3, e = w & 7;
    int cnt = 0;
    for (int t0 = 0; t0 < kT; t0 += 32) {
        int sel = (g_topi[(t0 + lane) * 2 + k] == e);
        cnt += __popc(__ballot_sync(0xffffffffu, sel));
    }
    if (lane == 0) kept[k][e] = min(cnt, kCap);
    __syncthreads();
    int off = (k == 0) ? 0 : kept[0][e];
    if (w < kE && lane == 0) g_cnt[w] = kept[0][w] + kept[1][w];
    int rank = 0;
    for (int t0 = 0; t0 < kT; t0 += 32) {
        int t = t0 + lane;
        int sel = (g_topi[t * 2 + k] == e);
        unsigned m = __ballot_sync(0xffffffffu, sel);
        int r = rank + __popc(m & ((1u << lane) - 1u));
        if (sel && r < kCap) {
            g_tok[e * kMaxN + off + r] = t;
            g_wt[e * kMaxN + off + r]  = g_topw[t * 2 + k];
        }
        rank += __popc(m);
    }
}

// ---------------- staging: gather x -> [hi|lo] rows ----------------
__global__ __launch_bounds__(256) void stage_x_kernel(const float* __restrict__ x) {
    int row = blockIdx.x * 8 + (threadIdx.x >> 5);
    int lane = threadIdx.x & 31;
    int e = row / kMaxN, m = row % kMaxN;
    if (m >= g_cnt[e]) return;
    const float* s = x + (size_t)g_tok[e * kMaxN + m] * kD;
    __nv_bfloat16* d = g_a + (size_t)row * 2 * kD;
#pragma unroll
    for (int i = 0; i < 32; i++) {
        float v = s[i * 32 + lane];
        __nv_bfloat16 h = __float2bfloat16(v);
        d[i * 32 + lane]      = h;
        d[kD + i * 32 + lane] = __float2bfloat16(v - __bfloat162float(h));
    }
}

// ---------------- staging: weights -> [hi|lo] rows (device-resolved dst) ----
__global__ __launch_bounds__(256) void repack_w_kernel(const float* __restrict__ src,
                                                       int which) {
    int row = blockIdx.x * 8 + (threadIdx.x >> 5);
    int lane = threadIdx.x & 31;
    __nv_bfloat16* dst = (which == 0) ? g_wg : (which == 1) ? g_wu : g_wd;
    int K = (which == 2) ? kH : kD;
    const float* s = src + (size_t)row * K;
    __nv_bfloat16* d = dst + (size_t)row * 2 * K;
    for (int i = lane; i < K; i += 32) {
        float v = s[i];
        __nv_bfloat16 h = __float2bfloat16(v);
        d[i]     = h;
        d[K + i] = __float2bfloat16(v - __bfloat162float(h));
    }
}

// ---------------------------------------------------------------------------
// HMMA GEMM, 3-term split in the K-schedule:
//   phase 0: A-hi x B-hi,  phase 1: A-lo x B-hi,  phase 2: A-hi x B-lo.
// BM=BN=128, BK=32, 8 warps (2x4, 64x32 warp tiles), 2-stage cp.async,
// 40KB static smem, pitch-80 rows (conflict-free ldmatrix).
// Operands resolved IN DEVICE CODE from the EPI selector:
//   EPI 0: A=g_a,   B=g_wu (K=kD, N=kH) -> store U hi/lo into g_act
//   EPI 1: A=g_a,   B=g_wg (K=kD, N=kH) -> act = silu(G)*U hi/lo (in place)
//   EPI 2: A=g_act, B=g_wd (K=kH, N=kD) -> weighted atomicAdd into out
// ---------------------------------------------------------------------------
template <int K, int EPI>
__global__ __launch_bounds__(256, 2) void hgemm_kernel(float* __restrict__ outp) {
    __shared__ __align__(16) char sm[2][20480];
    const __nv_bfloat16* A = (EPI == 2) ? g_act : g_a;
    const __nv_bfloat16* B = (EPI == 0) ? g_wu : (EPI == 1) ? g_wg : g_wd;
    constexpr int NTOT = (EPI == 2) ? kD : kH;

    int e = blockIdx.z, ne = g_cnt[e];
    int m0 = blockIdx.x * 128;             // x fastest: CTAs sharing B are adjacent
    if (m0 >= ne) return;
    int n0 = blockIdx.y * 128;
    int tid = threadIdx.x, warp = tid >> 5, lane = tid & 31;

    const char* Ab = (const char*)(A + ((size_t)e * kMaxN + m0) * (2 * K));
    const char* Bb = (const char*)(B + ((size_t)e * NTOT + n0) * (2 * K));
    constexpr int ROWB = 4 * K;            // bytes per [hi|lo] row
    constexpr int K32 = K / 32;
    constexpr int NC = 3 * K32;

    auto load = [&](int c, int s) {
        int p = c / K32, k = c % K32;
        int ca = (p == 1) ? K32 + k : k;   // A: lo plane only in phase 1
        int cb = (p == 2) ? K32 + k : k;   // B: lo plane only in phase 2
        uint32_t base = smem_u32(sm[s]);
#pragma unroll
        for (int i = 0; i < 2; i++) {
            int u = tid + 256 * i; int r = u >> 2, sg = u & 3;
            cp16(base + r * 80 + sg * 16,         Ab + (size_t)r * ROWB + ca * 64 + sg * 16);
            cp16(base + 10240 + r * 80 + sg * 16, Bb + (size_t)r * ROWB + cb * 64 + sg * 16);
        }
        cp_commit();
    };

    float acc[4][4][4];
#pragma unroll
    for (int a = 0; a < 4; a++)
#pragma unroll
        for (int b = 0; b < 4; b++)
#pragma unroll
            for (int c = 0; c < 4; c++) acc[a][b][c] = 0.f;

    int wm = (warp >> 2) * 64, wn = (warp & 3) * 32;
    int la = lane & 15, lk = lane >> 4;
    int lbr = lane & 7, lbk = (lane >> 3) & 1;

    load(0, 0);
    for (int c = 0; c < NC; c++) {
        cp_wait<0>();
        __syncthreads();
        if (c + 1 < NC) load(c + 1, (c + 1) & 1);

        uint32_t bA = smem_u32(sm[c & 1]);
        uint32_t bB = bA + 10240;
#pragma unroll
        for (int kk = 0; kk < 2; kk++) {
            uint32_t af[4][4], bf[4][2];
#pragma unroll
            for (int mt = 0; mt < 4; mt++)
                ldsm4(af[mt], bA + (wm + mt * 16 + la) * 80 + (kk * 16 + lk * 8) * 2);
#pragma unroll
            for (int nt = 0; nt < 4; nt++)
                ldsm2(bf[nt], bB + (wn + nt * 8 + lbr) * 80 + (kk * 16 + lbk * 8) * 2);
#pragma unroll
            for (int mt = 0; mt < 4; mt++)
#pragma unroll
                for (int nt = 0; nt < 4; nt++)
                    mma16816(acc[mt][nt], af[mt], bf[nt]);
        }
        __syncthreads();
    }

    // ---- epilogue ----
    int r0 = wm + (lane >> 2);
    int cb0 = wn + (lane & 3) * 2;
    size_t rowbase = (size_t)e * kMaxN + m0;

    if (EPI == 0) {                        // store U hi/lo
#pragma unroll
        for (int mt = 0; mt < 4; mt++)
#pragma unroll
            for (int h = 0; h < 2; h++) {
                int ml = r0 + mt * 16 + h * 8;
                __nv_bfloat16* drow = g_act + (rowbase + ml) * (size_t)(2 * kH);
#pragma unroll
                for (int nt = 0; nt < 4; nt++) {
                    int cc = n0 + cb0 + nt * 8;
                    float v0 = acc[mt][nt][h * 2], v1 = acc[mt][nt][h * 2 + 1];
                    __nv_bfloat16 h0 = __float2bfloat16(v0), h1 = __float2bfloat16(v1);
                    *(uint32_t*)(drow + cc)      = pack2(h0, h1);
                    *(uint32_t*)(drow + kH + cc) = pack2(
                        __float2bfloat16(v0 - __bfloat162float(h0)),
                        __float2bfloat16(v1 - __bfloat162float(h1)));
                }
            }
    } else if (EPI == 1) {                 // act = silu(G) * U, in place
#pragma unroll
        for (int mt = 0; mt < 4; mt++)
#pragma unroll
            for (int h = 0; h < 2; h++) {
                int ml = r0 + mt * 16 + h * 8;
                __nv_bfloat16* drow = g_act + (rowbase + ml) * (size_t)(2 * kH);
#pragma unroll
                for (int nt = 0; nt < 4; nt++) {
                    int cc = n0 + cb0 + nt * 8;
                    float u0 = __bfloat162float(drow[cc]) + __bfloat162float(drow[kH + cc]);
                    float u1 = __bfloat162float(drow[cc + 1]) + __bfloat162float(drow[kH + cc + 1]);
                    float g0 = acc[mt][nt][h * 2], g1 = acc[mt][nt][h * 2 + 1];
                    float v0 = u0 * g0 / (1.f + expf(-g0));
                    float v1 = u1 * g1 / (1.f + expf(-g1));
                    __nv_bfloat16 h0 = __float2bfloat16(v0), h1 = __float2bfloat16(v1);
                    *(uint32_t*)(drow + cc)      = pack2(h0, h1);
                    *(uint32_t*)(drow + kH + cc) = pack2(
                        __float2bfloat16(v0 - __bfloat162float(h0)),
                        __float2bfloat16(v1 - __bfloat162float(h1)));
                }
            }
    } else {                               // weighted scatter-add
#pragma unroll
        for (int mt = 0; mt < 4; mt++)
#pragma unroll
            for (int h = 0; h < 2; h++) {
                int ml = r0 + mt * 16 + h * 8;
                if (m0 + ml < ne) {
                    int tok  = g_tok[e * kMaxN + m0 + ml];
                    float wt = g_wt[e * kMaxN + m0 + ml];
                    float* orow = outp + (size_t)tok * kD + n0;
#pragma unroll
                    for (int nt = 0; nt < 4; nt++) {
                        atomicAdd(&orow[cb0 + nt * 8],     wt * acc[mt][nt][h * 2]);
                        atomicAdd(&orow[cb0 + nt * 8 + 1], wt * acc[mt][nt][h * 2 + 1]);
                    }
                }
            }
    }
}

// ---------------- launch ----------------
extern "C" void kernel_launch(void* const* d_in, const int* in_sizes, int n_in,
                              void* d_out, int out_size) {
    (void)in_sizes; (void)n_in;
    const float* x  = (const float*)d_in[0];
    const float* gw = (const float*)d_in[1];
    const float* wg = (const float*)d_in[2];
    const float* wu = (const float*)d_in[3];
    const float* wd = (const float*)d_in[4];
    float* out = (float*)d_out;

    cudaMemsetAsync(out, 0, (size_t)out_size * sizeof(float));

    router_kernel<<<kT / 8, 256>>>(x, gw);
    build_lists_kernel<<<1, 512>>>();
    stage_x_kernel<<<kE * kMaxN / 8, 256>>>(x);
    repack_w_kernel<<<kE * kH / 8, 256>>>(wg, 0);
    repack_w_kernel<<<kE * kH / 8, 256>>>(wu, 1);
    repack_w_kernel<<<kE * kD / 8, 256>>>(wd, 2);

    dim3 gGU(kMaxN / 128, kH / 128, kE);   // (20, 16, 8)
    hgemm_kernel<kD, 0><<<gGU, 256>>>(nullptr);   // UP
    hgemm_kernel<kD, 1><<<gGU, 256>>>(nullptr);   // GATE + SwiGLU

    dim3 gDN(kMaxN / 128, kD / 128, kE);   // (20, 8, 8)
    hgemm_kernel<kH, 2><<<gDN, 256>>>(out);       // DOWN + scatter
}

// round 12
// speedup vs baseline: 3.0193x; 1.9856x over previous
#include <cuda_runtime.h>
#include <cuda_bf16.h>
#include <cstdint>

namespace {
constexpr int kT = 8192, kD = 1024, kH = 2048, kE = 8, kK = 2;
constexpr int kCap = 1280, kMaxN = 2560;
constexpr int PA  = kMaxN / 128;  // 20 panels (A rows / act rows)
constexpr int PGU = kH / 128;     // 16 panels (gate/up weight rows)
constexpr int PD  = kD / 128;     // 8 panels (down weight rows)
}

// ---------------- device scratch (device-code references ONLY) -------------
__device__ int   g_topi[kT * kK];
__device__ float g_topw[kT * kK];
__device__ int   g_tok[kE * kMaxN];
__device__ float g_wt [kE * kMaxN];
__device__ int   g_cnt[kE];
// Chunk-blocked swizzled buffers. Block = 8KB: 128 rows x 4 x 16B units,
// unit (r,c) stored at swz(r,c) = r*4 + (c ^ ((r>>1)&3)). 16B unit holds 8
// consecutive k-elements (bf16). Block index: ((e*P + panel)*2 + plane)*CH + ch.
__device__ __align__(128) __nv_bfloat16 g_a  [(size_t)kE * PA  * 2 * 32 * 4096];
__device__ __align__(128) __nv_bfloat16 g_wg [(size_t)kE * PGU * 2 * 32 * 4096];
__device__ __align__(128) __nv_bfloat16 g_wu [(size_t)kE * PGU * 2 * 32 * 4096];
__device__ __align__(128) __nv_bfloat16 g_wd [(size_t)kE * PD  * 2 * 64 * 4096];
__device__ __align__(128) __nv_bfloat16 g_act[(size_t)kE * PA  * 2 * 64 * 4096];

__device__ __forceinline__ int swz(int r, int c) { return r * 4 + (c ^ ((r >> 1) & 3)); }

// ---------------- PTX helpers ----------------
__device__ __forceinline__ uint32_t smem_u32(const void* p) {
    uint32_t a;
    asm("{ .reg .u64 t; cvta.to.shared.u64 t, %1; cvt.u32.u64 %0, t; }" : "=r"(a) : "l"(p));
    return a;
}
__device__ __forceinline__ void mbar_init(uint32_t a, uint32_t c) {
    asm volatile("mbarrier.init.shared.b64 [%0], %1;" :: "r"(a), "r"(c) : "memory");
}
__device__ __forceinline__ void mbar_arrive_tx(uint32_t a, uint32_t bytes) {
    asm volatile("mbarrier.arrive.expect_tx.shared.b64 _, [%0], %1;"
                 :: "r"(a), "r"(bytes) : "memory");
}
__device__ __forceinline__ void mbar_wait(uint32_t a, uint32_t par) {
    asm volatile("{\n\t.reg .pred P;\n\tW_%=:\n\t"
                 "mbarrier.try_wait.parity.acquire.cta.shared::cta.b64 P, [%0], %1, 0x989680;\n\t"
                 "@!P bra.uni W_%=;\n\t}" :: "r"(a), "r"(par) : "memory");
}
__device__ __forceinline__ void bulk_g2s(uint32_t dst, const void* src,
                                         uint32_t bytes, uint32_t mbar) {
    asm volatile("cp.async.bulk.shared::cta.global.mbarrier::complete_tx::bytes "
                 "[%0], [%1], %2, [%3];"
                 :: "r"(dst), "l"(src), "r"(bytes), "r"(mbar) : "memory");
}
__device__ __forceinline__ void ldsm4(uint32_t* r, uint32_t a) {
    asm volatile("ldmatrix.sync.aligned.m8n8.x4.shared.b16 {%0,%1,%2,%3}, [%4];"
                 : "=r"(r[0]), "=r"(r[1]), "=r"(r[2]), "=r"(r[3]) : "r"(a));
}
__device__ __forceinline__ void ldsm2(uint32_t* r, uint32_t a) {
    asm volatile("ldmatrix.sync.aligned.m8n8.x2.shared.b16 {%0,%1}, [%2];"
                 : "=r"(r[0]), "=r"(r[1]) : "r"(a));
}
__device__ __forceinline__ void mma16816(float* d, const uint32_t* a, const uint32_t* b) {
    asm volatile(
        "mma.sync.aligned.m16n8k16.row.col.f32.bf16.bf16.f32 "
        "{%0,%1,%2,%3}, {%4,%5,%6,%7}, {%8,%9}, {%0,%1,%2,%3};"
        : "+f"(d[0]), "+f"(d[1]), "+f"(d[2]), "+f"(d[3])
        : "r"(a[0]), "r"(a[1]), "r"(a[2]), "r"(a[3]), "r"(b[0]), "r"(b[1]));
}
__device__ __forceinline__ uint32_t pack2(__nv_bfloat16 a, __nv_bfloat16 b) {
    __nv_bfloat162 t(a, b);
    return *reinterpret_cast<uint32_t*>(&t);
}

// ---------------- router (verified) ----------------
__global__ __launch_bounds__(256) void router_kernel(const float* __restrict__ x,
                                                     const float* __restrict__ gw) {
    int lane = threadIdx.x & 31, warp = threadIdx.x >> 5;
    int t = blockIdx.x * 8 + warp;
    const float* xr = x + (size_t)t * kD;
    float xv[32];
#pragma unroll
    for (int i = 0; i < 32; i++) xv[i] = xr[lane + 32 * i];
    float lg[kE];
#pragma unroll
    for (int e = 0; e < kE; e++) {
        const float* g = gw + e * kD;
        float s = 0.f;
#pragma unroll
        for (int i = 0; i < 32; i++) s = fmaf(xv[i], g[lane + 32 * i], s);
#pragma unroll
        for (int o = 16; o > 0; o >>= 1) s += __shfl_xor_sync(0xffffffffu, s, o);
        lg[e] = s;
    }
    if (lane == 0) {
        float mx = lg[0];
#pragma unroll
        for (int e = 1; e < kE; e++) mx = fmaxf(mx, lg[e]);
        float p[kE], den = 0.f;
#pragma unroll
        for (int e = 0; e < kE; e++) { p[e] = expf(lg[e] - mx); den += p[e]; }
        int i1 = 0; float p1 = p[0];
#pragma unroll
        for (int e = 1; e < kE; e++) if (p[e] > p1) { p1 = p[e]; i1 = e; }
        int i2 = (i1 == 0) ? 1 : 0; float p2 = p[i2];
#pragma unroll
        for (int e = 0; e < kE; e++) if (e != i1 && p[e] > p2) { p2 = p[e]; i2 = e; }
        float a = p1 / den, b = p2 / den, inv = 1.f / (a + b + 1e-9f);
        g_topi[t * 2] = i1; g_topi[t * 2 + 1] = i2;
        g_topw[t * 2] = a * inv; g_topw[t * 2 + 1] = b * inv;
    }
}

// ---------------- capacity lists (verified) ----------------
__global__ __launch_bounds__(512) void build_lists_kernel() {
    __shared__ int kept[kK][kE];
    int w = threadIdx.x >> 5, lane = threadIdx.x & 31;
    int k = w >> 3, e = w & 7;
    int cnt = 0;
    for (int t0 = 0; t0 < kT; t0 += 32) {
        int sel = (g_topi[(t0 + lane) * 2 + k] == e);
        cnt += __popc(__ballot_sync(0xffffffffu, sel));
    }
    if (lane == 0) kept[k][e] = min(cnt, kCap);
    __syncthreads();
    int off = (k == 0) ? 0 : kept[0][e];
    if (w < kE && lane == 0) g_cnt[w] = kept[0][w] + kept[1][w];
    int rank = 0;
    for (int t0 = 0; t0 < kT; t0 += 32) {
        int t = t0 + lane;
        int sel = (g_topi[t * 2 + k] == e);
        unsigned m = __ballot_sync(0xffffffffu, sel);
        int r = rank + __popc(m & ((1u << lane) - 1u));
        if (sel && r < kCap) {
            g_tok[e * kMaxN + off + r] = t;
            g_wt[e * kMaxN + off + r]  = g_topw[t * 2 + k];
        }
        rank += __popc(m);
    }
}

// ---------------- staging: gather x -> swizzled A blocks ----------------
__global__ __launch_bounds__(256) void stage_x_kernel(const float* __restrict__ x) {
    int er = blockIdx.x * 8 + (threadIdx.x >> 5);
    int lane = threadIdx.x & 31;
    int e = er / kMaxN, m = er % kMaxN;
    if (m >= g_cnt[e]) return;
    const float* s = x + (size_t)g_tok[e * kMaxN + m] * kD;
    int r = m & 127, p = m >> 7;
#pragma unroll
    for (int it = 0; it < 4; it++) {
        int unit = it * 32 + lane;          // 128 16B-units per row (K=1024)
        int ch = unit >> 2, c = unit & 3;
        float v[8];
        *(float4*)&v[0] = *(const float4*)(s + unit * 8);
        *(float4*)&v[4] = *(const float4*)(s + unit * 8 + 4);
        __nv_bfloat16 hi[8], lo[8];
#pragma unroll
        for (int j = 0; j < 8; j++) {
            hi[j] = __float2bfloat16(v[j]);
            lo[j] = __float2bfloat16(v[j] - __bfloat162float(hi[j]));
        }
        size_t u = (size_t)swz(r, c) * 8;
        size_t bh = ((((size_t)e * PA + p) * 2 + 0) * 32 + ch) * 4096 + u;
        size_t bl = ((((size_t)e * PA + p) * 2 + 1) * 32 + ch) * 4096 + u;
        *(uint4*)(g_a + bh) = *(uint4*)hi;
        *(uint4*)(g_a + bl) = *(uint4*)lo;
    }
}

// ---------------- staging: weights -> swizzled blocks ----------------
__global__ __launch_bounds__(256) void repack_w_kernel(const float* __restrict__ src,
                                                       int which) {
    int row = blockIdx.x * 8 + (threadIdx.x >> 5);
    int lane = threadIdx.x & 31;
    __nv_bfloat16* dst = (which == 0) ? g_wg : (which == 1) ? g_wu : g_wd;
    int P  = (which == 2) ? PD : PGU;
    int CH = (which == 2) ? 64 : 32;
    int K  = CH * 32;
    int e = row / (P * 128), n = row % (P * 128);
    int r = n & 127, p = n >> 7;
    const float* s = src + (size_t)row * K;
    int units = K / 8;
    for (int unit = lane; unit < units; unit += 32) {
        int ch = unit >> 2, c = unit & 3;
        float v[8];
        *(float4*)&v[0] = *(const float4*)(s + unit * 8);
        *(float4*)&v[4] = *(const float4*)(s + unit * 8 + 4);
        __nv_bfloat16 hi[8], lo[8];
#pragma unroll
        for (int j = 0; j < 8; j++) {
            hi[j] = __float2bfloat16(v[j]);
            lo[j] = __float2bfloat16(v[j] - __bfloat162float(hi[j]));
        }
        size_t u = (size_t)swz(r, c) * 8;
        size_t bh = ((((size_t)e * P + p) * 2 + 0) * CH + ch) * 4096 + u;
        size_t bl = ((((size_t)e * P + p) * 2 + 1) * CH + ch) * 4096 + u;
        *(uint4*)(dst + bh) = *(uint4*)hi;
        *(uint4*)(dst + bl) = *(uint4*)lo;
    }
}

// ---------------------------------------------------------------------------
// Merged GATE+UP GEMM. BM=BN=128, BK=32, 3-term split in the K-schedule
// (phase0 Ahi*Bhi, phase1 Alo*Bhi, phase2 Ahi*Blo), bulk-copy 3-stage
// pipeline (24KB/stage: A|BG|BU). Epilogue: act = silu(G)*U -> hi/lo blocks.
// ---------------------------------------------------------------------------
__global__ __launch_bounds__(256, 1) void gu_kernel() {
    extern __shared__ __align__(128) char dsm[];
    __shared__ __align__(8) unsigned long long mb[3];
    int e = blockIdx.z, ne = g_cnt[e];
    int m0 = blockIdx.x * 128;
    if (m0 >= ne) return;
    int n0 = blockIdx.y * 128;
    int tid = threadIdx.x, warp = tid >> 5, lane = tid & 31;
    uint32_t sb = smem_u32(dsm);
    uint32_t mbu = smem_u32(mb);
    int pa = m0 >> 7, pb = n0 >> 7;

    if (tid == 0) { mbar_init(mbu, 1); mbar_init(mbu + 8, 1); mbar_init(mbu + 16, 1); }
    __syncthreads();

    auto arm = [&](int c, int s) {
        int phs = c >> 5, k = c & 31;
        int apl = (phs == 1), bpl = (phs == 2);
        const __nv_bfloat16* sa = g_a  + ((((size_t)e * PA  + pa) * 2 + apl) * 32 + k) * 4096;
        const __nv_bfloat16* sg = g_wg + ((((size_t)e * PGU + pb) * 2 + bpl) * 32 + k) * 4096;
        const __nv_bfloat16* su = g_wu + ((((size_t)e * PGU + pb) * 2 + bpl) * 32 + k) * 4096;
        uint32_t st = sb + s * 24576;
        mbar_arrive_tx(mbu + s * 8, 24576);
        bulk_g2s(st,         sa, 8192, mbu + s * 8);
        bulk_g2s(st + 8192,  sg, 8192, mbu + s * 8);
        bulk_g2s(st + 16384, su, 8192, mbu + s * 8);
    };
    if (tid == 0) { arm(0, 0); arm(1, 1); arm(2, 2); }

    float accG[4][4][4], accU[4][4][4];
#pragma unroll
    for (int a = 0; a < 4; a++)
#pragma unroll
        for (int b = 0; b < 4; b++)
#pragma unroll
            for (int c = 0; c < 4; c++) { accG[a][b][c] = 0.f; accU[a][b][c] = 0.f; }

    int wm = (warp >> 2) * 64, wn = (warp & 3) * 32;
    int la = lane & 15, lk = lane >> 4;
    int lbr = lane & 7, lbk = (lane >> 3) & 1;
    uint32_t ph[3] = {0, 0, 0};
    const int NC = 96;

    for (int c = 0; c < NC; c++) {
        int s = c % 3;
        mbar_wait(mbu + s * 8, ph[s]); ph[s] ^= 1;
        uint32_t bA = sb + s * 24576, bG = bA + 8192, bU = bA + 16384;
#pragma unroll
        for (int kk = 0; kk < 2; kk++) {
            uint32_t af[4][4], bg[4][2], bu[4][2];
#pragma unroll
            for (int mt = 0; mt < 4; mt++) {
                int r = wm + mt * 16 + la;
                ldsm4(af[mt], bA + swz(r, kk * 2 + lk) * 16);
            }
#pragma unroll
            for (int nt = 0; nt < 4; nt++) {
                int r = wn + nt * 8 + lbr;
                uint32_t u = swz(r, kk * 2 + lbk) * 16;
                ldsm2(bg[nt], bG + u);
                ldsm2(bu[nt], bU + u);
            }
#pragma unroll
            for (int mt = 0; mt < 4; mt++)
#pragma unroll
                for (int nt = 0; nt < 4; nt++) {
                    mma16816(accG[mt][nt], af[mt], bg[nt]);
                    mma16816(accU[mt][nt], af[mt], bu[nt]);
                }
        }
        __syncthreads();
        if (tid == 0 && c + 3 < NC) arm(c + 3, s);
    }

    // epilogue: act = silu(G)*U -> hi/lo blocks (down-GEMM layout)
    int r0 = wm + (lane >> 2);
    int cb0 = wn + (lane & 3) * 2;
#pragma unroll
    for (int mt = 0; mt < 4; mt++)
#pragma unroll
        for (int h = 0; h < 2; h++) {
            int ml = r0 + mt * 16 + h * 8;     // row within panel (all rows valid)
#pragma unroll
            for (int nt = 0; nt < 4; nt++) {
                int n = n0 + cb0 + nt * 8;
                float g0 = accG[mt][nt][h * 2], g1 = accG[mt][nt][h * 2 + 1];
                float u0 = accU[mt][nt][h * 2], u1 = accU[mt][nt][h * 2 + 1];
                float v0 = u0 * g0 / (1.f + expf(-g0));
                float v1 = u1 * g1 / (1.f + expf(-g1));
                __nv_bfloat16 h0 = __float2bfloat16(v0), h1 = __float2bfloat16(v1);
                uint32_t hp = pack2(h0, h1);
                uint32_t lp = pack2(__float2bfloat16(v0 - __bfloat162float(h0)),
                                    __float2bfloat16(v1 - __bfloat162float(h1)));
                int ch = n >> 5, cc = (n >> 3) & 3, sub = n & 7;
                size_t u = (size_t)swz(ml, cc) * 8 + sub;
                size_t bh = ((((size_t)e * PA + pa) * 2 + 0) * 64 + ch) * 4096 + u;
                size_t bl = ((((size_t)e * PA + pa) * 2 + 1) * 64 + ch) * 4096 + u;
                *(uint32_t*)(g_act + bh) = hp;
                *(uint32_t*)(g_act + bl) = lp;
            }
        }
}

// ---------------------------------------------------------------------------
// DOWN GEMM + weighted atomic scatter. Same structure, 16KB/stage, NC=192.
// ---------------------------------------------------------------------------
__global__ __launch_bounds__(256, 2) void down_kernel(float* __restrict__ out) {
    extern __shared__ __align__(128) char dsm[];
    __shared__ __align__(8) unsigned long long mb[3];
    int e = blockIdx.z, ne = g_cnt[e];
    int m0 = blockIdx.x * 128;
    if (m0 >= ne) return;
    int n0 = blockIdx.y * 128;
    int tid = threadIdx.x, warp = tid >> 5, lane = tid & 31;
    uint32_t sb = smem_u32(dsm);
    uint32_t mbu = smem_u32(mb);
    int pa = m0 >> 7, pb = n0 >> 7;

    if (tid == 0) { mbar_init(mbu, 1); mbar_init(mbu + 8, 1); mbar_init(mbu + 16, 1); }
    __syncthreads();

    auto arm = [&](int c, int s) {
        int phs = c >> 6, k = c & 63;
        int apl = (phs == 1), bpl = (phs == 2);
        const __nv_bfloat16* sa = g_act + ((((size_t)e * PA + pa) * 2 + apl) * 64 + k) * 4096;
        const __nv_bfloat16* sd = g_wd  + ((((size_t)e * PD + pb) * 2 + bpl) * 64 + k) * 4096;
        uint32_t st = sb + s * 16384;
        mbar_arrive_tx(mbu + s * 8, 16384);
        bulk_g2s(st,        sa, 8192, mbu + s * 8);
        bulk_g2s(st + 8192, sd, 8192, mbu + s * 8);
    };
    if (tid == 0) { arm(0, 0); arm(1, 1); arm(2, 2); }

    float acc[4][4][4];
#pragma unroll
    for (int a = 0; a < 4; a++)
#pragma unroll
        for (int b = 0; b < 4; b++)
#pragma unroll
            for (int c = 0; c < 4; c++) acc[a][b][c] = 0.f;

    int wm = (warp >> 2) * 64, wn = (warp & 3) * 32;
    int la = lane & 15, lk = lane >> 4;
    int lbr = lane & 7, lbk = (lane >> 3) & 1;
    uint32_t ph[3] = {0, 0, 0};
    const int NC = 192;

    for (int c = 0; c < NC; c++) {
        int s = c % 3;
        mbar_wait(mbu + s * 8, ph[s]); ph[s] ^= 1;
        uint32_t bA = sb + s * 16384, bB = bA + 8192;
#pragma unroll
        for (int kk = 0; kk < 2; kk++) {
            uint32_t af[4][4], bf[4][2];
#pragma unroll
            for (int mt = 0; mt < 4; mt++) {
                int r = wm + mt * 16 + la;
                ldsm4(af[mt], bA + swz(r, kk * 2 + lk) * 16);
            }
#pragma unroll
            for (int nt = 0; nt < 4; nt++) {
                int r = wn + nt * 8 + lbr;
                ldsm2(bf[nt], bB + swz(r, kk * 2 + lbk) * 16);
            }
#pragma unroll
            for (int mt = 0; mt < 4; mt++)
#pragma unroll
                for (int nt = 0; nt < 4; nt++)
                    mma16816(acc[mt][nt], af[mt], bf[nt]);
        }
        __syncthreads();
        if (tid == 0 && c + 3 < NC) arm(c + 3, s);
    }

    // epilogue: weighted scatter-add
    int r0 = wm + (lane >> 2);
    int cb0 = wn + (lane & 3) * 2;
#pragma unroll
    for (int mt = 0; mt < 4; mt++)
#pragma unroll
        for (int h = 0; h < 2; h++) {
            int ml = r0 + mt * 16 + h * 8;
            if (m0 + ml < ne) {
                int tok  = g_tok[e * kMaxN + m0 + ml];
                float wt = g_wt[e * kMaxN + m0 + ml];
                float* orow = out + (size_t)tok * kD + n0;
#pragma unroll
                for (int nt = 0; nt < 4; nt++) {
                    atomicAdd(&orow[cb0 + nt * 8],     wt * acc[mt][nt][h * 2]);
                    atomicAdd(&orow[cb0 + nt * 8 + 1], wt * acc[mt][nt][h * 2 + 1]);
                }
            }
        }
}

// ---------------- launch ----------------
extern "C" void kernel_launch(void* const* d_in, const int* in_sizes, int n_in,
                              void* d_out, int out_size) {
    (void)in_sizes; (void)n_in;
    const float* x  = (const float*)d_in[0];
    const float* gw = (const float*)d_in[1];
    const float* wg = (const float*)d_in[2];
    const float* wu = (const float*)d_in[3];
    const float* wd = (const float*)d_in[4];
    float* out = (float*)d_out;

    const int GU_SM = 3 * 24576;   // 73728
    const int DN_SM = 3 * 16384;   // 49152
    cudaFuncSetAttribute(gu_kernel,   cudaFuncAttributeMaxDynamicSharedMemorySize, GU_SM);
    cudaFuncSetAttribute(down_kernel, cudaFuncAttributeMaxDynamicSharedMemorySize, DN_SM);

    cudaMemsetAsync(out, 0, (size_t)out_size * sizeof(float));

    router_kernel<<<kT / 8, 256>>>(x, gw);
    build_lists_kernel<<<1, 512>>>();
    stage_x_kernel<<<kE * kMaxN / 8, 256>>>(x);
    repack_w_kernel<<<kE * kH / 8, 256>>>(wg, 0);
    repack_w_kernel<<<kE * kH / 8, 256>>>(wu, 1);
    repack_w_kernel<<<kE * kD / 8, 256>>>(wd, 2);

    dim3 gGU(kMaxN / 128, kH / 128, kE);   // (20, 16, 8)
    gu_kernel<<<gGU, 256, GU_SM>>>();

    dim3 gDN(kMaxN / 128, kD / 128, kE);   // (20, 8, 8)
    down_kernel<<<gDN, 256, DN_SM>>>(out);
}

// round 13
// speedup vs baseline: 3.3349x; 1.1045x over previous
#include <cuda_runtime.h>
#include <cuda_bf16.h>
#include <cstdint>

namespace {
constexpr int kT = 8192, kD = 1024, kH = 2048, kE = 8, kK = 2;
constexpr int kCap = 1280, kMaxN = 2560;
constexpr int PA  = kMaxN / 128;  // 20 panels (A rows / act rows)
constexpr int PGU = kH / 128;     // 16 panels (gate/up weight rows)
constexpr int PD  = kD / 128;     // 8 panels (down weight rows)
}

// ---------------- device scratch (device-code references ONLY) -------------
__device__ int   g_topi[kT * kK];
__device__ float g_topw[kT * kK];
__device__ int   g_tok[kE * kMaxN];
__device__ float g_wt [kE * kMaxN];
__device__ int   g_cnt[kE];
// Chunk-blocked swizzled buffers. Block = 8KB: 128 rows x 4 x 16B units,
// unit (r,c) stored at swz(r,c) = r*4 + (c ^ ((r>>1)&3)).
__device__ __align__(128) __nv_bfloat16 g_a  [(size_t)kE * PA  * 2 * 32 * 4096];
__device__ __align__(128) __nv_bfloat16 g_wg [(size_t)kE * PGU * 2 * 32 * 4096];
__device__ __align__(128) __nv_bfloat16 g_wu [(size_t)kE * PGU * 2 * 32 * 4096];
__device__ __align__(128) __nv_bfloat16 g_wd [(size_t)kE * PD  * 2 * 64 * 4096];
__device__ __align__(128) __nv_bfloat16 g_act[(size_t)kE * PA  * 2 * 64 * 4096];

__device__ __forceinline__ int swz(int r, int c) { return r * 4 + (c ^ ((r >> 1) & 3)); }

// ---------------- PTX helpers ----------------
__device__ __forceinline__ uint32_t smem_u32(const void* p) {
    uint32_t a;
    asm("{ .reg .u64 t; cvta.to.shared.u64 t, %1; cvt.u32.u64 %0, t; }" : "=r"(a) : "l"(p));
    return a;
}
__device__ __forceinline__ void mbar_init(uint32_t a, uint32_t c) {
    asm volatile("mbarrier.init.shared.b64 [%0], %1;" :: "r"(a), "r"(c) : "memory");
}
__device__ __forceinline__ void mbar_arrive(uint32_t a) {
    asm volatile("mbarrier.arrive.shared.b64 _, [%0];" :: "r"(a) : "memory");
}
__device__ __forceinline__ void mbar_arrive_tx(uint32_t a, uint32_t bytes) {
    asm volatile("mbarrier.arrive.expect_tx.shared.b64 _, [%0], %1;"
                 :: "r"(a), "r"(bytes) : "memory");
}
__device__ __forceinline__ void mbar_wait(uint32_t a, uint32_t par) {
    asm volatile("{\n\t.reg .pred P;\n\tW_%=:\n\t"
                 "mbarrier.try_wait.parity.acquire.cta.shared::cta.b64 P, [%0], %1, 0x989680;\n\t"
                 "@!P bra.uni W_%=;\n\t}" :: "r"(a), "r"(par) : "memory");
}
__device__ __forceinline__ void bulk_g2s(uint32_t dst, const void* src,
                                         uint32_t bytes, uint32_t mbar) {
    asm volatile("cp.async.bulk.shared::cta.global.mbarrier::complete_tx::bytes "
                 "[%0], [%1], %2, [%3];"
                 :: "r"(dst), "l"(src), "r"(bytes), "r"(mbar) : "memory");
}
__device__ __forceinline__ void ldsm4(uint32_t* r, uint32_t a) {
    asm volatile("ldmatrix.sync.aligned.m8n8.x4.shared.b16 {%0,%1,%2,%3}, [%4];"
                 : "=r"(r[0]), "=r"(r[1]), "=r"(r[2]), "=r"(r[3]) : "r"(a));
}
__device__ __forceinline__ void ldsm2(uint32_t* r, uint32_t a) {
    asm volatile("ldmatrix.sync.aligned.m8n8.x2.shared.b16 {%0,%1}, [%2];"
                 : "=r"(r[0]), "=r"(r[1]) : "r"(a));
}
__device__ __forceinline__ void mma16816(float* d, const uint32_t* a, const uint32_t* b) {
    asm volatile(
        "mma.sync.aligned.m16n8k16.row.col.f32.bf16.bf16.f32 "
        "{%0,%1,%2,%3}, {%4,%5,%6,%7}, {%8,%9}, {%0,%1,%2,%3};"
        : "+f"(d[0]), "+f"(d[1]), "+f"(d[2]), "+f"(d[3])
        : "r"(a[0]), "r"(a[1]), "r"(a[2]), "r"(a[3]), "r"(b[0]), "r"(b[1]));
}
__device__ __forceinline__ uint32_t pack2(__nv_bfloat16 a, __nv_bfloat16 b) {
    __nv_bfloat162 t(a, b);
    return *reinterpret_cast<uint32_t*>(&t);
}

// ---------------- router (verified) ----------------
__global__ __launch_bounds__(256) void router_kernel(const float* __restrict__ x,
                                                     const float* __restrict__ gw) {
    int lane = threadIdx.x & 31, warp = threadIdx.x >> 5;
    int t = blockIdx.x * 8 + warp;
    const float* xr = x + (size_t)t * kD;
    float xv[32];
#pragma unroll
    for (int i = 0; i < 32; i++) xv[i] = xr[lane + 32 * i];
    float lg[kE];
#pragma unroll
    for (int e = 0; e < kE; e++) {
        const float* g = gw + e * kD;
        float s = 0.f;
#pragma unroll
        for (int i = 0; i < 32; i++) s = fmaf(xv[i], g[lane + 32 * i], s);
#pragma unroll
        for (int o = 16; o > 0; o >>= 1) s += __shfl_xor_sync(0xffffffffu, s, o);
        lg[e] = s;
    }
    if (lane == 0) {
        float mx = lg[0];
#pragma unroll
        for (int e = 1; e < kE; e++) mx = fmaxf(mx, lg[e]);
        float p[kE], den = 0.f;
#pragma unroll
        for (int e = 0; e < kE; e++) { p[e] = expf(lg[e] - mx); den += p[e]; }
        int i1 = 0; float p1 = p[0];
#pragma unroll
        for (int e = 1; e < kE; e++) if (p[e] > p1) { p1 = p[e]; i1 = e; }
        int i2 = (i1 == 0) ? 1 : 0; float p2 = p[i2];
#pragma unroll
        for (int e = 0; e < kE; e++) if (e != i1 && p[e] > p2) { p2 = p[e]; i2 = e; }
        float a = p1 / den, b = p2 / den, inv = 1.f / (a + b + 1e-9f);
        g_topi[t * 2] = i1; g_topi[t * 2 + 1] = i2;
        g_topw[t * 2] = a * inv; g_topw[t * 2 + 1] = b * inv;
    }
}

// ---------------- capacity lists (verified) ----------------
__global__ __launch_bounds__(512) void build_lists_kernel() {
    __shared__ int kept[kK][kE];
    int w = threadIdx.x >> 5, lane = threadIdx.x & 31;
    int k = w >> 3, e = w & 7;
    int cnt = 0;
    for (int t0 = 0; t0 < kT; t0 += 32) {
        int sel = (g_topi[(t0 + lane) * 2 + k] == e);
        cnt += __popc(__ballot_sync(0xffffffffu, sel));
    }
    if (lane == 0) kept[k][e] = min(cnt, kCap);
    __syncthreads();
    int off = (k == 0) ? 0 : kept[0][e];
    if (w < kE && lane == 0) g_cnt[w] = kept[0][w] + kept[1][w];
    int rank = 0;
    for (int t0 = 0; t0 < kT; t0 += 32) {
        int t = t0 + lane;
        int sel = (g_topi[t * 2 + k] == e);
        unsigned m = __ballot_sync(0xffffffffu, sel);
        int r = rank + __popc(m & ((1u << lane) - 1u));
        if (sel && r < kCap) {
            g_tok[e * kMaxN + off + r] = t;
            g_wt[e * kMaxN + off + r]  = g_topw[t * 2 + k];
        }
        rank += __popc(m);
    }
}

// ---------------- staging: gather x -> swizzled A blocks ----------------
__global__ __launch_bounds__(256) void stage_x_kernel(const float* __restrict__ x) {
    int er = blockIdx.x * 8 + (threadIdx.x >> 5);
    int lane = threadIdx.x & 31;
    int e = er / kMaxN, m = er % kMaxN;
    if (m >= g_cnt[e]) return;
    const float* s = x + (size_t)g_tok[e * kMaxN + m] * kD;
    int r = m & 127, p = m >> 7;
#pragma unroll
    for (int it = 0; it < 4; it++) {
        int unit = it * 32 + lane;
        int ch = unit >> 2, c = unit & 3;
        float v[8];
        *(float4*)&v[0] = *(const float4*)(s + unit * 8);
        *(float4*)&v[4] = *(const float4*)(s + unit * 8 + 4);
        __nv_bfloat16 hi[8], lo[8];
#pragma unroll
        for (int j = 0; j < 8; j++) {
            hi[j] = __float2bfloat16(v[j]);
            lo[j] = __float2bfloat16(v[j] - __bfloat162float(hi[j]));
        }
        size_t u = (size_t)swz(r, c) * 8;
        size_t bh = ((((size_t)e * PA + p) * 2 + 0) * 32 + ch) * 4096 + u;
        size_t bl = ((((size_t)e * PA + p) * 2 + 1) * 32 + ch) * 4096 + u;
        *(uint4*)(g_a + bh) = *(uint4*)hi;
        *(uint4*)(g_a + bl) = *(uint4*)lo;
    }
}

// ---------------- staging: weights -> swizzled blocks ----------------
__global__ __launch_bounds__(256) void repack_w_kernel(const float* __restrict__ src,
                                                       int which) {
    int row = blockIdx.x * 8 + (threadIdx.x >> 5);
    int lane = threadIdx.x & 31;
    __nv_bfloat16* dst = (which == 0) ? g_wg : (which == 1) ? g_wu : g_wd;
    int P  = (which == 2) ? PD : PGU;
    int CH = (which == 2) ? 64 : 32;
    int K  = CH * 32;
    int e = row / (P * 128), n = row % (P * 128);
    int r = n & 127, p = n >> 7;
    const float* s = src + (size_t)row * K;
    int units = K / 8;
    for (int unit = lane; unit < units; unit += 32) {
        int ch = unit >> 2, c = unit & 3;
        float v[8];
        *(float4*)&v[0] = *(const float4*)(s + unit * 8);
        *(float4*)&v[4] = *(const float4*)(s + unit * 8 + 4);
        __nv_bfloat16 hi[8], lo[8];
#pragma unroll
        for (int j = 0; j < 8; j++) {
            hi[j] = __float2bfloat16(v[j]);
            lo[j] = __float2bfloat16(v[j] - __bfloat162float(hi[j]));
        }
        size_t u = (size_t)swz(r, c) * 8;
        size_t bh = ((((size_t)e * P + p) * 2 + 0) * CH + ch) * 4096 + u;
        size_t bl = ((((size_t)e * P + p) * 2 + 1) * CH + ch) * 4096 + u;
        *(uint4*)(dst + bh) = *(uint4*)hi;
        *(uint4*)(dst + bl) = *(uint4*)lo;
    }
}

// ---------------------------------------------------------------------------
// Merged GATE+UP GEMM, producer/consumer mbarrier pipeline.
// 288 threads: warps 0-7 compute (2x4 layout, 64x32 warp tiles), warp 8 =
// producer (one elected thread issues bulk copies). 5 stages x 24KB.
// Full[s]: expect_tx(24KB) + 3 bulk copies. Empty[s]: 8 warp-arrivals.
// Parity: consumer waits (c/S)&1 on full; producer waits ((c/S)&1)^1 on empty.
// ---------------------------------------------------------------------------
__global__ __launch_bounds__(288, 1) void gu_kernel() {
    constexpr int S = 5;
    constexpr int NC = 96;
    extern __shared__ __align__(128) char dsm[];
    __shared__ __align__(8) unsigned long long mbF[S], mbE[S];
    int e = blockIdx.z, ne = g_cnt[e];
    int m0 = blockIdx.x * 128;
    if (m0 >= ne) return;
    int n0 = blockIdx.y * 128;
    int tid = threadIdx.x, warp = tid >> 5, lane = tid & 31;
    uint32_t sb = smem_u32(dsm);
    uint32_t mf = smem_u32(mbF), me = smem_u32(mbE);
    int pa = m0 >> 7, pb = n0 >> 7;

    if (tid == 0)
        for (int s = 0; s < S; s++) { mbar_init(mf + 8 * s, 1); mbar_init(me + 8 * s, 8); }
    __syncthreads();

    if (warp == 8) {
        if (lane == 0) {   // producer
            for (int c = 0; c < NC; c++) {
                int s = c % S;
                mbar_wait(me + 8 * s, ((c / S) & 1) ^ 1);
                int phs = c >> 5, k = c & 31;
                int apl = (phs == 1), bpl = (phs == 2);
                const __nv_bfloat16* sa = g_a  + ((((size_t)e * PA  + pa) * 2 + apl) * 32 + k) * 4096;
                const __nv_bfloat16* sg = g_wg + ((((size_t)e * PGU + pb) * 2 + bpl) * 32 + k) * 4096;
                const __nv_bfloat16* su = g_wu + ((((size_t)e * PGU + pb) * 2 + bpl) * 32 + k) * 4096;
                uint32_t st = sb + s * 24576;
                mbar_arrive_tx(mf + 8 * s, 24576);
                bulk_g2s(st,         sa, 8192, mf + 8 * s);
                bulk_g2s(st + 8192,  sg, 8192, mf + 8 * s);
                bulk_g2s(st + 16384, su, 8192, mf + 8 * s);
            }
        }
        return;   // producer warp: no epilogue
    }

    float accG[4][4][4], accU[4][4][4];
#pragma unroll
    for (int a = 0; a < 4; a++)
#pragma unroll
        for (int b = 0; b < 4; b++)
#pragma unroll
            for (int c = 0; c < 4; c++) { accG[a][b][c] = 0.f; accU[a][b][c] = 0.f; }

    int wm = (warp >> 2) * 64, wn = (warp & 3) * 32;
    int la = lane & 15, lk = lane >> 4;
    int lbr = lane & 7, lbk = (lane >> 3) & 1;

    for (int c = 0; c < NC; c++) {
        int s = c % S;
        mbar_wait(mf + 8 * s, (c / S) & 1);
        uint32_t bA = sb + s * 24576, bG = bA + 8192, bU = bA + 16384;
#pragma unroll
        for (int kk = 0; kk < 2; kk++) {
            uint32_t af[4][4], bg[4][2], bu[4][2];
#pragma unroll
            for (int mt = 0; mt < 4; mt++) {
                int r = wm + mt * 16 + la;
                ldsm4(af[mt], bA + swz(r, kk * 2 + lk) * 16);
            }
#pragma unroll
            for (int nt = 0; nt < 4; nt++) {
                int r = wn + nt * 8 + lbr;
                uint32_t u = swz(r, kk * 2 + lbk) * 16;
                ldsm2(bg[nt], bG + u);
                ldsm2(bu[nt], bU + u);
            }
#pragma unroll
            for (int mt = 0; mt < 4; mt++)
#pragma unroll
                for (int nt = 0; nt < 4; nt++) {
                    mma16816(accG[mt][nt], af[mt], bg[nt]);
                    mma16816(accU[mt][nt], af[mt], bu[nt]);
                }
        }
        if (lane == 0) mbar_arrive(me + 8 * s);   // smem reads done (mma issued)
    }

    // epilogue: act = silu(G)*U -> hi/lo blocks (down-GEMM layout)
    int r0 = wm + (lane >> 2);
    int cb0 = wn + (lane & 3) * 2;
#pragma unroll
    for (int mt = 0; mt < 4; mt++)
#pragma unroll
        for (int h = 0; h < 2; h++) {
            int ml = r0 + mt * 16 + h * 8;
#pragma unroll
            for (int nt = 0; nt < 4; nt++) {
                int n = n0 + cb0 + nt * 8;
                float g0 = accG[mt][nt][h * 2], g1 = accG[mt][nt][h * 2 + 1];
                float u0 = accU[mt][nt][h * 2], u1 = accU[mt][nt][h * 2 + 1];
                float v0 = u0 * g0 / (1.f + expf(-g0));
                float v1 = u1 * g1 / (1.f + expf(-g1));
                __nv_bfloat16 h0 = __float2bfloat16(v0), h1 = __float2bfloat16(v1);
                uint32_t hp = pack2(h0, h1);
                uint32_t lp = pack2(__float2bfloat16(v0 - __bfloat162float(h0)),
                                    __float2bfloat16(v1 - __bfloat162float(h1)));
                int ch = n >> 5, cc = (n >> 3) & 3, sub = n & 7;
                size_t u = (size_t)swz(ml, cc) * 8 + sub;
                size_t bh = ((((size_t)e * PA + pa) * 2 + 0) * 64 + ch) * 4096 + u;
                size_t bl = ((((size_t)e * PA + pa) * 2 + 1) * 64 + ch) * 4096 + u;
                *(uint32_t*)(g_act + bh) = hp;
                *(uint32_t*)(g_act + bl) = lp;
            }
        }
}

// ---------------------------------------------------------------------------
// DOWN GEMM + weighted atomic scatter. Same pipeline, 6 stages x 16KB.
// ---------------------------------------------------------------------------
__global__ __launch_bounds__(288, 1) void down_kernel(float* __restrict__ out) {
    constexpr int S = 6;
    constexpr int NC = 192;
    extern __shared__ __align__(128) char dsm[];
    __shared__ __align__(8) unsigned long long mbF[S], mbE[S];
    int e = blockIdx.z, ne = g_cnt[e];
    int m0 = blockIdx.x * 128;
    if (m0 >= ne) return;
    int n0 = blockIdx.y * 128;
    int tid = threadIdx.x, warp = tid >> 5, lane = tid & 31;
    uint32_t sb = smem_u32(dsm);
    uint32_t mf = smem_u32(mbF), me = smem_u32(mbE);
    int pa = m0 >> 7, pb = n0 >> 7;

    if (tid == 0)
        for (int s = 0; s < S; s++) { mbar_init(mf + 8 * s, 1); mbar_init(me + 8 * s, 8); }
    __syncthreads();

    if (warp == 8) {
        if (lane == 0) {
            for (int c = 0; c < NC; c++) {
                int s = c % S;
                mbar_wait(me + 8 * s, ((c / S) & 1) ^ 1);
                int phs = c >> 6, k = c & 63;
                int apl = (phs == 1), bpl = (phs == 2);
                const __nv_bfloat16* sa = g_act + ((((size_t)e * PA + pa) * 2 + apl) * 64 + k) * 4096;
                const __nv_bfloat16* sd = g_wd  + ((((size_t)e * PD + pb) * 2 + bpl) * 64 + k) * 4096;
                uint32_t st = sb + s * 16384;
                mbar_arrive_tx(mf + 8 * s, 16384);
                bulk_g2s(st,        sa, 8192, mf + 8 * s);
                bulk_g2s(st + 8192, sd, 8192, mf + 8 * s);
            }
        }
        return;
    }

    float acc[4][4][4];
#pragma unroll
    for (int a = 0; a < 4; a++)
#pragma unroll
        for (int b = 0; b < 4; b++)
#pragma unroll
            for (int c = 0; c < 4; c++) acc[a][b][c] = 0.f;

    int wm = (warp >> 2) * 64, wn = (warp & 3) * 32;
    int la = lane & 15, lk = lane >> 4;
    int lbr = lane & 7, lbk = (lane >> 3) & 1;

    for (int c = 0; c < NC; c++) {
        int s = c % S;
        mbar_wait(mf + 8 * s, (c / S) & 1);
        uint32_t bA = sb + s * 16384, bB = bA + 8192;
#pragma unroll
        for (int kk = 0; kk < 2; kk++) {
            uint32_t af[4][4], bf[4][2];
#pragma unroll
            for (int mt = 0; mt < 4; mt++) {
                int r = wm + mt * 16 + la;
                ldsm4(af[mt], bA + swz(r, kk * 2 + lk) * 16);
            }
#pragma unroll
            for (int nt = 0; nt < 4; nt++) {
                int r = wn + nt * 8 + lbr;
                ldsm2(bf[nt], bB + swz(r, kk * 2 + lbk) * 16);
            }
#pragma unroll
            for (int mt = 0; mt < 4; mt++)
#pragma unroll
                for (int nt = 0; nt < 4; nt++)
                    mma16816(acc[mt][nt], af[mt], bf[nt]);
        }
        if (lane == 0) mbar_arrive(me + 8 * s);
    }

    // epilogue: weighted scatter-add
    int r0 = wm + (lane >> 2);
    int cb0 = wn + (lane & 3) * 2;
#pragma unroll
    for (int mt = 0; mt < 4; mt++)
#pragma unroll
        for (int h = 0; h < 2; h++) {
            int ml = r0 + mt * 16 + h * 8;
            if (m0 + ml < ne) {
                int tok  = g_tok[e * kMaxN + m0 + ml];
                float wt = g_wt[e * kMaxN + m0 + ml];
                float* orow = out + (size_t)tok * kD + n0;
#pragma unroll
                for (int nt = 0; nt < 4; nt++) {
                    atomicAdd(&orow[cb0 + nt * 8],     wt * acc[mt][nt][h * 2]);
                    atomicAdd(&orow[cb0 + nt * 8 + 1], wt * acc[mt][nt][h * 2 + 1]);
                }
            }
        }
}

// ---------------- launch ----------------
extern "C" void kernel_launch(void* const* d_in, const int* in_sizes, int n_in,
                              void* d_out, int out_size) {
    (void)in_sizes; (void)n_in;
    const float* x  = (const float*)d_in[0];
    const float* gw = (const float*)d_in[1];
    const float* wg = (const float*)d_in[2];
    const float* wu = (const float*)d_in[3];
    const float* wd = (const float*)d_in[4];
    float* out = (float*)d_out;

    const int GU_SM = 5 * 24576;   // 122880
    const int DN_SM = 6 * 16384;   // 98304
    cudaFuncSetAttribute(gu_kernel,   cudaFuncAttributeMaxDynamicSharedMemorySize, GU_SM);
    cudaFuncSetAttribute(down_kernel, cudaFuncAttributeMaxDynamicSharedMemorySize, DN_SM);

    cudaMemsetAsync(out, 0, (size_t)out_size * sizeof(float));

    router_kernel<<<kT / 8, 256>>>(x, gw);
    build_lists_kernel<<<1, 512>>>();
    stage_x_kernel<<<kE * kMaxN / 8, 256>>>(x);
    repack_w_kernel<<<kE * kH / 8, 256>>>(wg, 0);
    repack_w_kernel<<<kE * kH / 8, 256>>>(wu, 1);
    repack_w_kernel<<<kE * kD / 8, 256>>>(wd, 2);

    dim3 gGU(kMaxN / 128, kH / 128, kE);   // (20, 16, 8)
    gu_kernel<<<gGU, 288, GU_SM>>>();

    dim3 gDN(kMaxN / 128, kD / 128, kE);   // (20, 8, 8)
    down_kernel<<<gDN, 288, DN_SM>>>(out);
}

// round 16
// speedup vs baseline: 3.5116x; 1.0530x over previous
#include <cuda_runtime.h>
#include <cuda_bf16.h>
#include <cstdint>

namespace {
constexpr int kT = 8192, kD = 1024, kH = 2048, kE = 8, kK = 2;
constexpr int kCap = 1280, kMaxN = 2560;
constexpr int PA  = kMaxN / 128;  // 20 panels (A rows / act rows)
constexpr int PGU = kH / 128;     // 16 panels (gate/up weight rows)
constexpr int PD  = kD / 128;     // 8 panels (down weight rows)
}

// ---------------- device scratch (device-code references ONLY) -------------
__device__ int   g_topi[kT * kK];
__device__ float g_topw[kT * kK];
__device__ int   g_tok[kE * kMaxN];
__device__ float g_wt [kE * kMaxN];
__device__ int   g_cnt[kE];
// Chunk-blocked swizzled buffers. Block = 8KB: 128 rows x 4 x 16B units,
// unit (r,c) stored at swz(r,c) = r*4 + (c ^ ((r>>1)&3)).
__device__ __align__(128) __nv_bfloat16 g_a  [(size_t)kE * PA  * 2 * 32 * 4096];
__device__ __align__(128) __nv_bfloat16 g_wg [(size_t)kE * PGU * 2 * 32 * 4096];
__device__ __align__(128) __nv_bfloat16 g_wu [(size_t)kE * PGU * 2 * 32 * 4096];
__device__ __align__(128) __nv_bfloat16 g_wd [(size_t)kE * PD  * 2 * 64 * 4096];
__device__ __align__(128) __nv_bfloat16 g_act[(size_t)kE * PA  * 2 * 64 * 4096];

__device__ __forceinline__ int swz(int r, int c) { return r * 4 + (c ^ ((r >> 1) & 3)); }

// ---------------- PTX helpers ----------------
__device__ __forceinline__ uint32_t smem_u32(const void* p) {
    uint32_t a;
    asm("{ .reg .u64 t; cvta.to.shared.u64 t, %1; cvt.u32.u64 %0, t; }" : "=r"(a) : "l"(p));
    return a;
}
__device__ __forceinline__ void mbar_init(uint32_t a, uint32_t c) {
    asm volatile("mbarrier.init.shared.b64 [%0], %1;" :: "r"(a), "r"(c) : "memory");
}
__device__ __forceinline__ void mbar_arrive(uint32_t a) {
    asm volatile("mbarrier.arrive.shared.b64 _, [%0];" :: "r"(a) : "memory");
}
__device__ __forceinline__ void mbar_arrive_tx(uint32_t a, uint32_t bytes) {
    asm volatile("mbarrier.arrive.expect_tx.shared.b64 _, [%0], %1;"
                 :: "r"(a), "r"(bytes) : "memory");
}
__device__ __forceinline__ void mbar_wait(uint32_t a, uint32_t par) {
    asm volatile("{\n\t.reg .pred P;\n\tW_%=:\n\t"
                 "mbarrier.try_wait.parity.acquire.cta.shared::cta.b64 P, [%0], %1, 0x989680;\n\t"
                 "@!P bra.uni W_%=;\n\t}" :: "r"(a), "r"(par) : "memory");
}
__device__ __forceinline__ void bulk_g2s(uint32_t dst, const void* src,
                                         uint32_t bytes, uint32_t mbar) {
    asm volatile("cp.async.bulk.shared::cta.global.mbarrier::complete_tx::bytes "
                 "[%0], [%1], %2, [%3];"
                 :: "r"(dst), "l"(src), "r"(bytes), "r"(mbar) : "memory");
}
__device__ __forceinline__ void ldsm4(uint32_t* r, uint32_t a) {
    asm volatile("ldmatrix.sync.aligned.m8n8.x4.shared.b16 {%0,%1,%2,%3}, [%4];"
                 : "=r"(r[0]), "=r"(r[1]), "=r"(r[2]), "=r"(r[3]) : "r"(a));
}
__device__ __forceinline__ void ldsm2(uint32_t* r, uint32_t a) {
    asm volatile("ldmatrix.sync.aligned.m8n8.x2.shared.b16 {%0,%1}, [%2];"
                 : "=r"(r[0]), "=r"(r[1]) : "r"(a));
}
__device__ __forceinline__ void mma16816(float* d, const uint32_t* a, const uint32_t* b) {
    asm volatile(
        "mma.sync.aligned.m16n8k16.row.col.f32.bf16.bf16.f32 "
        "{%0,%1,%2,%3}, {%4,%5,%6,%7}, {%8,%9}, {%0,%1,%2,%3};"
        : "+f"(d[0]), "+f"(d[1]), "+f"(d[2]), "+f"(d[3])
        : "r"(a[0]), "r"(a[1]), "r"(a[2]), "r"(a[3]), "r"(b[0]), "r"(b[1]));
}
__device__ __forceinline__ uint32_t pack2(__nv_bfloat16 a, __nv_bfloat16 b) {
    __nv_bfloat162 t(a, b);
    return *reinterpret_cast<uint32_t*>(&t);
}

// ---------------- router (verified) ----------------
__global__ __launch_bounds__(256) void router_kernel(const float* __restrict__ x,
                                                     const float* __restrict__ gw) {
    int lane = threadIdx.x & 31, warp = threadIdx.x >> 5;
    int t = blockIdx.x * 8 + warp;
    const float* xr = x + (size_t)t * kD;
    float xv[32];
#pragma unroll
    for (int i = 0; i < 32; i++) xv[i] = xr[lane + 32 * i];
    float lg[kE];
#pragma unroll
    for (int e = 0; e < kE; e++) {
        const float* g = gw + e * kD;
        float s = 0.f;
#pragma unroll
        for (int i = 0; i < 32; i++) s = fmaf(xv[i], g[lane + 32 * i], s);
#pragma unroll
        for (int o = 16; o > 0; o >>= 1) s += __shfl_xor_sync(0xffffffffu, s, o);
        lg[e] = s;
    }
    if (lane == 0) {
        float mx = lg[0];
#pragma unroll
        for (int e = 1; e < kE; e++) mx = fmaxf(mx, lg[e]);
        float p[kE], den = 0.f;
#pragma unroll
        for (int e = 0; e < kE; e++) { p[e] = expf(lg[e] - mx); den += p[e]; }
        int i1 = 0; float p1 = p[0];
#pragma unroll
        for (int e = 1; e < kE; e++) if (p[e] > p1) { p1 = p[e]; i1 = e; }
        int i2 = (i1 == 0) ? 1 : 0; float p2 = p[i2];
#pragma unroll
        for (int e = 0; e < kE; e++) if (e != i1 && p[e] > p2) { p2 = p[e]; i2 = e; }
        float a = p1 / den, b = p2 / den, inv = 1.f / (a + b + 1e-9f);
        g_topi[t * 2] = i1; g_topi[t * 2 + 1] = i2;
        g_topw[t * 2] = a * inv; g_topw[t * 2 + 1] = b * inv;
    }
}

// ---------------- capacity lists (verified) ----------------
__global__ __launch_bounds__(512) void build_lists_kernel() {
    __shared__ int kept[kK][kE];
    int w = threadIdx.x >> 5, lane = threadIdx.x & 31;
    int k = w >> 3, e = w & 7;
    int cnt = 0;
    for (int t0 = 0; t0 < kT; t0 += 32) {
        int sel = (g_topi[(t0 + lane) * 2 + k] == e);
        cnt += __popc(__ballot_sync(0xffffffffu, sel));
    }
    if (lane == 0) kept[k][e] = min(cnt, kCap);
    __syncthreads();
    int off = (k == 0) ? 0 : kept[0][e];
    if (w < kE && lane == 0) g_cnt[w] = kept[0][w] + kept[1][w];
    int rank = 0;
    for (int t0 = 0; t0 < kT; t0 += 32) {
        int t = t0 + lane;
        int sel = (g_topi[t * 2 + k] == e);
        unsigned m = __ballot_sync(0xffffffffu, sel);
        int r = rank + __popc(m & ((1u << lane) - 1u));
        if (sel && r < kCap) {
            g_tok[e * kMaxN + off + r] = t;
            g_wt[e * kMaxN + off + r]  = g_topw[t * 2 + k];
        }
        rank += __popc(m);
    }
}

// ---------------- staging: gather x -> swizzled A blocks ----------------
__global__ __launch_bounds__(256) void stage_x_kernel(const float* __restrict__ x) {
    int er = blockIdx.x * 8 + (threadIdx.x >> 5);
    int lane = threadIdx.x & 31;
    int e = er / kMaxN, m = er % kMaxN;
    if (m >= g_cnt[e]) return;
    const float* s = x + (size_t)g_tok[e * kMaxN + m] * kD;
    int r = m & 127, p = m >> 7;
#pragma unroll
    for (int it = 0; it < 4; it++) {
        int unit = it * 32 + lane;
        int ch = unit >> 2, c = unit & 3;
        float v[8];
        *(float4*)&v[0] = *(const float4*)(s + unit * 8);
        *(float4*)&v[4] = *(const float4*)(s + unit * 8 + 4);
        __nv_bfloat16 hi[8], lo[8];
#pragma unroll
        for (int j = 0; j < 8; j++) {
            hi[j] = __float2bfloat16(v[j]);
            lo[j] = __float2bfloat16(v[j] - __bfloat162float(hi[j]));
        }
        size_t u = (size_t)swz(r, c) * 8;
        size_t bh = ((((size_t)e * PA + p) * 2 + 0) * 32 + ch) * 4096 + u;
        size_t bl = ((((size_t)e * PA + p) * 2 + 1) * 32 + ch) * 4096 + u;
        *(uint4*)(g_a + bh) = *(uint4*)hi;
        *(uint4*)(g_a + bl) = *(uint4*)lo;
    }
}

// ---------------- staging: ALL weights in one launch ----------------
// rows [0, E*H)          -> wg
// rows [E*H, 2*E*H)      -> wu
// rows [2*E*H, 2*E*H+E*D)-> wd
__global__ __launch_bounds__(256) void repack_all_kernel(const float* __restrict__ wg,
                                                         const float* __restrict__ wu,
                                                         const float* __restrict__ wd) {
    int grow = blockIdx.x * 8 + (threadIdx.x >> 5);
    int lane = threadIdx.x & 31;
    const float* src;
    __nv_bfloat16* dst;
    int row, P, CH;
    if (grow < kE * kH)            { src = wg; dst = g_wg; row = grow;              P = PGU; CH = 32; }
    else if (grow < 2 * kE * kH)   { src = wu; dst = g_wu; row = grow - kE * kH;    P = PGU; CH = 32; }
    else                           { src = wd; dst = g_wd; row = grow - 2 * kE * kH; P = PD; CH = 64; }
    int K = CH * 32;
    int e = row / (P * 128), n = row % (P * 128);
    int r = n & 127, p = n >> 7;
    const float* s = src + (size_t)row * K;
    int units = K / 8;
    for (int unit = lane; unit < units; unit += 32) {
        int ch = unit >> 2, c = unit & 3;
        float v[8];
        *(float4*)&v[0] = *(const float4*)(s + unit * 8);
        *(float4*)&v[4] = *(const float4*)(s + unit * 8 + 4);
        __nv_bfloat16 hi[8], lo[8];
#pragma unroll
        for (int j = 0; j < 8; j++) {
            hi[j] = __float2bfloat16(v[j]);
            lo[j] = __float2bfloat16(v[j] - __bfloat162float(hi[j]));
        }
        size_t u = (size_t)swz(r, c) * 8;
        size_t bh = ((((size_t)e * P + p) * 2 + 0) * CH + ch) * 4096 + u;
        size_t bl = ((((size_t)e * P + p) * 2 + 1) * CH + ch) * 4096 + u;
        *(uint4*)(dst + bh) = *(uint4*)hi;
        *(uint4*)(dst + bl) = *(uint4*)lo;
    }
}

// ---------------------------------------------------------------------------
// Merged GATE+UP GEMM, producer/consumer pipeline, BK=64 chunks.
// 288 threads: warps 0-7 compute (2x4, 64x32 warp tiles), warp 8 producer.
// Stage = 48KB: [A0 A1 | G0 G1 | U0 U1] (6 x 8KB blocks), S=3 stages.
// NC = 48 chunks (3 phases x 16). Full[s]: expect_tx(48KB)+6 bulk copies.
// Empty[s]: 8 warp arrivals. Parity: consumer (c/S)&1, producer ^1.
// ---------------------------------------------------------------------------
__global__ __launch_bounds__(288, 1) void gu_kernel() {
    constexpr int S = 3;
    constexpr int NC = 48;
    extern __shared__ __align__(128) char dsm[];
    __shared__ __align__(8) unsigned long long mbF[S], mbE[S];
    int e = blockIdx.z, ne = g_cnt[e];
    int m0 = blockIdx.x * 128;
    if (m0 >= ne) return;
    int n0 = blockIdx.y * 128;
    int tid = threadIdx.x, warp = tid >> 5, lane = tid & 31;
    uint32_t sb = smem_u32(dsm);
    uint32_t mf = smem_u32(mbF), me = smem_u32(mbE);
    int pa = m0 >> 7, pb = n0 >> 7;

    if (tid == 0)
        for (int s = 0; s < S; s++) { mbar_init(mf + 8 * s, 1); mbar_init(me + 8 * s, 8); }
    __syncthreads();

    if (warp == 8) {
        if (lane == 0) {   // producer
            for (int c = 0; c < NC; c++) {
                int s = c % S;
                mbar_wait(me + 8 * s, ((c / S) & 1) ^ 1);
                int phs = c >> 4, k2 = (c & 15) * 2;     // two 8KB blocks per chunk
                int apl = (phs == 1), bpl = (phs == 2);
                const __nv_bfloat16* sa = g_a  + ((((size_t)e * PA  + pa) * 2 + apl) * 32 + k2) * 4096;
                const __nv_bfloat16* sg = g_wg + ((((size_t)e * PGU + pb) * 2 + bpl) * 32 + k2) * 4096;
                const __nv_bfloat16* su = g_wu + ((((size_t)e * PGU + pb) * 2 + bpl) * 32 + k2) * 4096;
                uint32_t st = sb + s * 49152;
                mbar_arrive_tx(mf + 8 * s, 49152);
                bulk_g2s(st,         sa, 16384, mf + 8 * s);   // A0+A1 contiguous
                bulk_g2s(st + 16384, sg, 16384, mf + 8 * s);   // G0+G1
                bulk_g2s(st + 32768, su, 16384, mf + 8 * s);   // U0+U1
            }
        }
        return;
    }

    float accG[4][4][4], accU[4][4][4];
#pragma unroll
    for (int a = 0; a < 4; a++)
#pragma unroll
        for (int b = 0; b < 4; b++)
#pragma unroll
            for (int c = 0; c < 4; c++) { accG[a][b][c] = 0.f; accU[a][b][c] = 0.f; }

    int wm = (warp >> 2) * 64, wn = (warp & 3) * 32;
    int la = lane & 15, lk = lane >> 4;
    int lbr = lane & 7, lbk = (lane >> 3) & 1;

    for (int c = 0; c < NC; c++) {
        int s = c % S;
        mbar_wait(mf + 8 * s, (c / S) & 1);
        uint32_t st = sb + s * 49152;
#pragma unroll
        for (int blk = 0; blk < 2; blk++) {
            uint32_t bA = st + blk * 8192;
            uint32_t bG = st + 16384 + blk * 8192;
            uint32_t bU = st + 32768 + blk * 8192;
#pragma unroll
            for (int kk = 0; kk < 2; kk++) {
                uint32_t af[4][4], bg[4][2], bu[4][2];
#pragma unroll
                for (int mt = 0; mt < 4; mt++) {
                    int r = wm + mt * 16 + la;
                    ldsm4(af[mt], bA + swz(r, kk * 2 + lk) * 16);
                }
#pragma unroll
                for (int nt = 0; nt < 4; nt++) {
                    int r = wn + nt * 8 + lbr;
                    uint32_t u = swz(r, kk * 2 + lbk) * 16;
                    ldsm2(bg[nt], bG + u);
                    ldsm2(bu[nt], bU + u);
                }
#pragma unroll
                for (int mt = 0; mt < 4; mt++)
#pragma unroll
                    for (int nt = 0; nt < 4; nt++) {
                        mma16816(accG[mt][nt], af[mt], bg[nt]);
                        mma16816(accU[mt][nt], af[mt], bu[nt]);
                    }
            }
        }
        if (lane == 0) mbar_arrive(me + 8 * s);
    }

    // epilogue: act = silu(G)*U -> hi/lo blocks (down-GEMM layout)
    int r0 = wm + (lane >> 2);
    int cb0 = wn + (lane & 3) * 2;
#pragma unroll
    for (int mt = 0; mt < 4; mt++)
#pragma unroll
        for (int h = 0; h < 2; h++) {
            int ml = r0 + mt * 16 + h * 8;
#pragma unroll
            for (int nt = 0; nt < 4; nt++) {
                int n = n0 + cb0 + nt * 8;
                float g0 = accG[mt][nt][h * 2], g1 = accG[mt][nt][h * 2 + 1];
                float u0 = accU[mt][nt][h * 2], u1 = accU[mt][nt][h * 2 + 1];
                float v0 = u0 * g0 / (1.f + expf(-g0));
                float v1 = u1 * g1 / (1.f + expf(-g1));
                __nv_bfloat16 h0 = __float2bfloat16(v0), h1 = __float2bfloat16(v1);
                uint32_t hp = pack2(h0, h1);
                uint32_t lp = pack2(__float2bfloat16(v0 - __bfloat162float(h0)),
                                    __float2bfloat16(v1 - __bfloat162float(h1)));
                int ch = n >> 5, cc = (n >> 3) & 3, sub = n & 7;
                size_t u = (size_t)swz(ml, cc) * 8 + sub;
                size_t bh = ((((size_t)e * PA + pa) * 2 + 0) * 64 + ch) * 4096 + u;
                size_t bl = ((((size_t)e * PA + pa) * 2 + 1) * 64 + ch) * 4096 + u;
                *(uint32_t*)(g_act + bh) = hp;
                *(uint32_t*)(g_act + bl) = lp;
            }
        }
}

// ---------------------------------------------------------------------------
// DOWN GEMM + weighted atomic scatter. BK=64, stage=32KB [A0 A1 | D0 D1],
// S=4 stages, NC=96.
// ---------------------------------------------------------------------------
__global__ __launch_bounds__(288, 1) void down_kernel(float* __restrict__ out) {
    constexpr int S = 4;
    constexpr int NC = 96;
    extern __shared__ __align__(128) char dsm[];
    __shared__ __align__(8) unsigned long long mbF[S], mbE[S];
    int e = blockIdx.z, ne = g_cnt[e];
    int m0 = blockIdx.x * 128;
    if (m0 >= ne) return;
    int n0 = blockIdx.y * 128;
    int tid = threadIdx.x, warp = tid >> 5, lane = tid & 31;
    uint32_t sb = smem_u32(dsm);
    uint32_t mf = smem_u32(mbF), me = smem_u32(mbE);
    int pa = m0 >> 7, pb = n0 >> 7;

    if (tid == 0)
        for (int s = 0; s < S; s++) { mbar_init(mf + 8 * s, 1); mbar_init(me + 8 * s, 8); }
    __syncthreads();

    if (warp == 8) {
        if (lane == 0) {
            for (int c = 0; c < NC; c++) {
                int s = c % S;
                mbar_wait(me + 8 * s, ((c / S) & 1) ^ 1);
                int phs = c >> 5, k2 = (c & 31) * 2;
                int apl = (phs == 1), bpl = (phs == 2);
                const __nv_bfloat16* sa = g_act + ((((size_t)e * PA + pa) * 2 + apl) * 64 + k2) * 4096;
                const __nv_bfloat16* sd = g_wd  + ((((size_t)e * PD + pb) * 2 + bpl) * 64 + k2) * 4096;
                uint32_t st = sb + s * 32768;
                mbar_arrive_tx(mf + 8 * s, 32768);
                bulk_g2s(st,         sa, 16384, mf + 8 * s);
                bulk_g2s(st + 16384, sd, 16384, mf + 8 * s);
            }
        }
        return;
    }

    float acc[4][4][4];
#pragma unroll
    for (int a = 0; a < 4; a++)
#pragma unroll
        for (int b = 0; b < 4; b++)
#pragma unroll
            for (int c = 0; c < 4; c++) acc[a][b][c] = 0.f;

    int wm = (warp >> 2) * 64, wn = (warp & 3) * 32;
    int la = lane & 15, lk = lane >> 4;
    int lbr = lane & 7, lbk = (lane >> 3) & 1;

    for (int c = 0; c < NC; c++) {
        int s = c % S;
        mbar_wait(mf + 8 * s, (c / S) & 1);
        uint32_t st = sb + s * 32768;
#pragma unroll
        for (int blk = 0; blk < 2; blk++) {
            uint32_t bA = st + blk * 8192;
            uint32_t bB = st + 16384 + blk * 8192;
#pragma unroll
            for (int kk = 0; kk < 2; kk++) {
                uint32_t af[4][4], bf[4][2];
#pragma unroll
                for (int mt = 0; mt < 4; mt++) {
                    int r = wm + mt * 16 + la;
                    ldsm4(af[mt], bA + swz(r, kk * 2 + lk) * 16);
                }
#pragma unroll
                for (int nt = 0; nt < 4; nt++) {
                    int r = wn + nt * 8 + lbr;
                    ldsm2(bf[nt], bB + swz(r, kk * 2 + lbk) * 16);
                }
#pragma unroll
                for (int mt = 0; mt < 4; mt++)
#pragma unroll
                    for (int nt = 0; nt < 4; nt++)
                        mma16816(acc[mt][nt], af[mt], bf[nt]);
            }
        }
        if (lane == 0) mbar_arrive(me + 8 * s);
    }

    // epilogue: weighted scatter-add
    int r0 = wm + (lane >> 2);
    int cb0 = wn + (lane & 3) * 2;
#pragma unroll
    for (int mt = 0; mt < 4; mt++)
#pragma unroll
        for (int h = 0; h < 2; h++) {
            int ml = r0 + mt * 16 + h * 8;
            if (m0 + ml < ne) {
                int tok  = g_tok[e * kMaxN + m0 + ml];
                float wt = g_wt[e * kMaxN + m0 + ml];
                float* orow = out + (size_t)tok * kD + n0;
#pragma unroll
                for (int nt = 0; nt < 4; nt++) {
                    atomicAdd(&orow[cb0 + nt * 8],     wt * acc[mt][nt][h * 2]);
                    atomicAdd(&orow[cb0 + nt * 8 + 1], wt * acc[mt][nt][h * 2 + 1]);
                }
            }
        }
}

// ---------------- launch ----------------
extern "C" void kernel_launch(void* const* d_in, const int* in_sizes, int n_in,
                              void* d_out, int out_size) {
    (void)in_sizes; (void)n_in;
    const float* x  = (const float*)d_in[0];
    const float* gw = (const float*)d_in[1];
    const float* wg = (const float*)d_in[2];
    const float* wu = (const float*)d_in[3];
    const float* wd = (const float*)d_in[4];
    float* out = (float*)d_out;

    const int GU_SM = 3 * 49152;   // 147456
    const int DN_SM = 4 * 32768;   // 131072
    cudaFuncSetAttribute(gu_kernel,   cudaFuncAttributeMaxDynamicSharedMemorySize, GU_SM);
    cudaFuncSetAttribute(down_kernel, cudaFuncAttributeMaxDynamicSharedMemorySize, DN_SM);

    // Launch order fixed so ncu's (-s 5 -c 1) window lands on gu_kernel:
    // 0 memset, 1 router, 2 build, 3 stage_x, 4 repack_all, 5 gu, 6 down.
    cudaMemsetAsync(out, 0, (size_t)out_size * sizeof(float));
    router_kernel<<<kT / 8, 256>>>(x, gw);
    build_lists_kernel<<<1, 512>>>();
    stage_x_kernel<<<kE * kMaxN / 8, 256>>>(x);
    repack_all_kernel<<<(2 * kE * kH + kE * kD) / 8, 256>>>(wg, wu, wd);

    dim3 gGU(kMaxN / 128, kH / 128, kE);   // (20, 16, 8)
    gu_kernel<<<gGU, 288, GU_SM>>>();

    dim3 gDN(kMaxN / 128, kD / 128, kE);   // (20, 8, 8)
    down_kernel<<<gDN, 288, DN_SM>>>(out);
}